// round 11
// baseline (speedup 1.0000x reference)
#include <cuda_runtime.h>
#include <cuda_bf16.h>
#include <cuda_fp16.h>
#include <math.h>
#include <stdint.h>

#define BATCH   32768
#define D_IN    512
#define D_DENSE 256
#define TSTEPS  16
#define FEAT    16
#define H1      128
#define H2      32
#define NCLS    10

// ---------------- gmem state ----------------
__device__ __half g_acthi[D_DENSE * BATCH], g_actlo[D_DENSE * BATCH];  // col-major [feat][batch]
__device__ __half g_h2fhi[H2 * BATCH], g_h2flo[H2 * BATCH];            // final h2, col-major
__device__ float g_c1[H1 * BATCH], g_c2[H2 * BATCH];

// prepacked weights (gate-interleaved rows n=4u+g)
__device__ __half g_Wp1[(4 * H1) * (FEAT + H1)];   // [512][144] fp16
__device__ __half g_Wp2[(4 * H2) * (H1 + H2)];     // [128][160] fp16
__device__ __nv_bfloat16 g_WpD[D_DENSE * 2 * D_IN];
__device__ float g_bc1[4 * H1], g_bc2[4 * H2];
__device__ float g_d1sc[D_DENSE], g_d1sh[D_DENSE];

// ---------------- helpers ----------------
__device__ __forceinline__ uint32_t smem_u32(const void* p) {
    uint32_t a;
    asm("{ .reg .u64 t; cvta.to.shared.u64 t, %1; cvt.u32.u64 %0, t; }" : "=r"(a) : "l"(p));
    return a;
}
__device__ __forceinline__ float ftanh(float x) {
    float y;
    asm("tanh.approx.f32 %0, %1;" : "=f"(y) : "f"(x));
    return y;
}
__device__ __forceinline__ float fsigm(float x) { return 0.5f * ftanh(0.5f * x) + 0.5f; }

__device__ __forceinline__ void ldsm4(uint32_t* r, uint32_t addr) {
    asm volatile("ldmatrix.sync.aligned.m8n8.x4.shared.b16 {%0,%1,%2,%3}, [%4];"
                 : "=r"(r[0]), "=r"(r[1]), "=r"(r[2]), "=r"(r[3]) : "r"(addr));
}
__device__ __forceinline__ void ldsm4t(uint32_t* r, uint32_t addr) {
    asm volatile("ldmatrix.sync.aligned.m8n8.x4.trans.shared.b16 {%0,%1,%2,%3}, [%4];"
                 : "=r"(r[0]), "=r"(r[1]), "=r"(r[2]), "=r"(r[3]) : "r"(addr));
}
__device__ __forceinline__ void mma16816bf(float* d, const uint32_t* a, uint32_t b0, uint32_t b1) {
    asm volatile(
        "mma.sync.aligned.m16n8k16.row.col.f32.bf16.bf16.f32 "
        "{%0,%1,%2,%3}, {%4,%5,%6,%7}, {%8,%9}, {%0,%1,%2,%3};"
        : "+f"(d[0]), "+f"(d[1]), "+f"(d[2]), "+f"(d[3])
        : "r"(a[0]), "r"(a[1]), "r"(a[2]), "r"(a[3]), "r"(b0), "r"(b1));
}
__device__ __forceinline__ void mma16816h(float* d, const uint32_t* a, uint32_t b0, uint32_t b1) {
    asm volatile(
        "mma.sync.aligned.m16n8k16.row.col.f32.f16.f16.f32 "
        "{%0,%1,%2,%3}, {%4,%5,%6,%7}, {%8,%9}, {%0,%1,%2,%3};"
        : "+f"(d[0]), "+f"(d[1]), "+f"(d[2]), "+f"(d[3])
        : "r"(a[0]), "r"(a[1]), "r"(a[2]), "r"(a[3]), "r"(b0), "r"(b1));
}
__device__ __forceinline__ void cp16(uint32_t dst, const void* src) {
    asm volatile("cp.async.cg.shared.global [%0], [%1], 16;" :: "r"(dst), "l"(src));
}
#define CP_COMMIT() asm volatile("cp.async.commit_group;" ::: "memory")
#define CP_WAIT(n)  asm volatile("cp.async.wait_group %0;" :: "n"(n) : "memory")
#define CLUSTER_SYNC() do { \
    asm volatile("barrier.cluster.arrive.aligned;" ::: "memory"); \
    asm volatile("barrier.cluster.wait.aligned;" ::: "memory"); \
} while (0)

__device__ __forceinline__ void st_peer16(uint32_t laddr, uint32_t peer, uint16_t v) {
    uint32_t ra;
    asm volatile("mapa.shared::cluster.u32 %0, %1, %2;" : "=r"(ra) : "r"(laddr), "r"(peer));
    asm volatile("st.shared::cluster.b16 [%0], %1;" :: "r"(ra), "h"(v) : "memory");
}

// ================== persistent cluster RNN kernel ==================
// cluster of 2 CTAs owns 128 batch rows; CTA rank r computes gate-cols
// [r*256, r*256+256) of LSTM1 (units [r*64,+64)) and [r*64,+64) of LSTM2
// (units [r*16,+16)); h halves exchanged via DSMEM each step.
#define SROW 136
#define SB1  152
#define SB2  168
#define A1_OFF 0                      // 288 rows x 136 halfs (hi:0-143, lo:144-287; x rows 0-15/144-159)
#define A2_OFF 78336                  // 64 rows x 136 (h2 hi 0-31, lo 32-63)
#define B1_OFF (A2_OFF + 17408)       // 95744: 256 x 152 halfs
#define B2_OFF (B1_OFF + 77824)       // 173568: 64 x 168 halfs
#define SMEM_RNN (B2_OFF + 21504)     // 195072

__global__ __launch_bounds__(512, 1) __cluster_dims__(2, 1, 1)
void rnn_kernel() {
    extern __shared__ char smem[];
    const uint32_t sb = smem_u32(smem);
    const int tid = threadIdx.x;
    const int lane = tid & 31, wid = tid >> 5;
    uint32_t rank;
    asm("mov.u32 %0, %%cluster_ctarank;" : "=r"(rank));
    const uint32_t peer = rank ^ 1;
    const int m0 = (int)(blockIdx.x >> 1) * 128;
    __half* const A1h = (__half*)(smem + A1_OFF);
    __half* const A2h = (__half*)(smem + A2_OFF);

    // ---- prologue: load resident B1/B2, x(0); zero h regions ----
    for (int task = tid; task < 256 * 18; task += 512) {
        const int n = task / 18, gg = task % 18;
        cp16(sb + B1_OFF + (uint32_t)(n * SB1 + gg * 8) * 2,
             g_Wp1 + (size_t)(rank * 256 + n) * 144 + gg * 8);
    }
    for (int task = tid; task < 64 * 20; task += 512) {
        const int n = task / 20, gg = task % 20;
        cp16(sb + B2_OFF + (uint32_t)(n * SB2 + gg * 8) * 2,
             g_Wp2 + (size_t)(rank * 64 + n) * 160 + gg * 8);
    }
    for (int task = tid; task < 512; task += 512) {
        const int part = task >> 8, f = (task >> 4) & 15, mg = task & 15;
        const __half* src = (part ? g_actlo : g_acthi) + (size_t)f * BATCH + m0 + mg * 8;
        cp16(sb + A1_OFF + (uint32_t)((part * 144 + f) * SROW + mg * 8) * 2, src);
    }
    CP_COMMIT();
    for (int i = tid; i < 128 * SROW; i += 512) {
        A1h[16 * SROW + i] = __ushort_as_half(0);     // h1 hi rows 16..143
        A1h[160 * SROW + i] = __ushort_as_half(0);    // h1 lo rows 160..287
    }
    for (int i = tid; i < 64 * SROW; i += 512) A2h[i] = __ushort_as_half(0);
    CP_WAIT(0);
    __syncthreads();

    // warp geometry
    const int wm = wid & 3;                    // M quadrant (both layers)
    const int wn = wid >> 2;                   // LSTM1 N quadrant (0..3)
    const int wn2 = (wid >> 2) & 1;            // LSTM2 N half (warps 0-7)
    const uint32_t arow = (uint32_t)((lane & 7) + ((lane >> 4) << 3));
    const uint32_t acol = (uint32_t)(wm * 32 + (((lane >> 3) & 1) << 3));
    const uint32_t brow1 = (uint32_t)(wn * 64 + ((lane >> 4) << 3) + (lane & 7));
    const uint32_t brow2 = (uint32_t)(wn2 * 32 + ((lane >> 4) << 3) + (lane & 7));
    const uint32_t bcol8 = (uint32_t)(((lane >> 3) & 1) << 3);
    const int g = lane >> 2;
    const bool odd = lane & 1;

    for (int t = 0; t < TSTEPS; t++) {
        // ======== LSTM1 GEMM: M128 x N256(this CTA) x K144 (hi+lo) ========
        float acc[2][8][4] = {};
#pragma unroll 3
        for (int kk = 0; kk < 9; kk++) {
            uint32_t ah0[4], ah1[4], al0[4], al1[4];
            const uint32_t hr = (uint32_t)(kk * 16) + arow;
            ldsm4t(ah0, sb + A1_OFF + (hr * SROW + acol) * 2);
            ldsm4t(ah1, sb + A1_OFF + (hr * SROW + acol + 16) * 2);
            ldsm4t(al0, sb + A1_OFF + ((144 + hr) * SROW + acol) * 2);
            ldsm4t(al1, sb + A1_OFF + ((144 + hr) * SROW + acol + 16) * 2);
#pragma unroll
            for (int nj = 0; nj < 4; nj++) {
                uint32_t b[4];
                ldsm4(b, sb + B1_OFF + ((brow1 + nj * 16) * SB1 + (uint32_t)(kk * 16) + bcol8) * 2);
                mma16816h(acc[0][2 * nj], ah0, b[0], b[1]);
                mma16816h(acc[0][2 * nj + 1], ah0, b[2], b[3]);
                mma16816h(acc[1][2 * nj], ah1, b[0], b[1]);
                mma16816h(acc[1][2 * nj + 1], ah1, b[2], b[3]);
                mma16816h(acc[0][2 * nj], al0, b[0], b[1]);
                mma16816h(acc[0][2 * nj + 1], al0, b[2], b[3]);
                mma16816h(acc[1][2 * nj], al1, b[0], b[1]);
                mma16816h(acc[1][2 * nj + 1], al1, b[2], b[3]);
            }
        }
        CLUSTER_SYNC();   // (1) all A1 reads (both CTAs) done

        // ---- epilogue1: gates -> c1 gmem, h1 -> local + peer smem ----
#pragma unroll
        for (int ni = 0; ni < 8; ni++) {
            const int u = (((int)rank * 256 + wn * 64 + ni * 8) >> 2) + ((lane & 2) >> 1);
            const float4 bb = *(const float4*)(g_bc1 + 4 * u);
#pragma unroll
            for (int mi = 0; mi < 2; mi++) {
                const float d0 = acc[mi][ni][0], d1 = acc[mi][ni][1];
                const float d2 = acc[mi][ni][2], d3 = acc[mi][ni][3];
                const float s0 = __shfl_xor_sync(0xffffffffu, odd ? d0 : d2, 1);
                const float s1 = __shfl_xor_sync(0xffffffffu, odd ? d1 : d3, 1);
                const float zi = (odd ? s0 : d0) + bb.x;
                const float zf = (odd ? s1 : d1) + bb.y;
                const float zg = (odd ? d2 : s0) + bb.z;
                const float zo = (odd ? d3 : s1) + bb.w;
                const int row_l = wm * 32 + mi * 16 + g + (odd ? 8 : 0);
                const float ig = fsigm(zi);
                const float fg = fsigm(zf);
                const float gg = ftanh(zg);
                const float og = fsigm(zo);
                const size_t coff = (size_t)u * BATCH + m0 + row_l;
                const float cn = fg * g_c1[coff] + ig * gg;
                g_c1[coff] = cn;
                const float hv = og * ftanh(cn);
                const __half hh = __float2half_rn(hv);
                const __half hl = __float2half_rn(hv - __half2float(hh));
                const uint32_t ohi = (uint32_t)((16 + u) * SROW + row_l);
                const uint32_t olo = (uint32_t)((160 + u) * SROW + row_l);
                A1h[ohi] = hh;
                A1h[olo] = hl;
                st_peer16(sb + A1_OFF + ohi * 2, peer, __half_as_ushort(hh));
                st_peer16(sb + A1_OFF + olo * 2, peer, __half_as_ushort(hl));
            }
        }
        CLUSTER_SYNC();   // (2) new h1 visible everywhere

        // ======== LSTM2 (warps 0-7): M128 x N64(this CTA) x K160 ========
        float acc2[2][4][4] = {};
        if (wid < 8) {
#pragma unroll 2
            for (int kk = 0; kk < 10; kk++) {
                uint32_t ah0[4], ah1[4], al0[4], al1[4];
                uint32_t base_hi, base_lo;
                if (kk < 8) {
                    base_hi = sb + A1_OFF + (((uint32_t)(16 + kk * 16) + arow) * SROW) * 2;
                    base_lo = sb + A1_OFF + (((uint32_t)(160 + kk * 16) + arow) * SROW) * 2;
                } else {
                    base_hi = sb + A2_OFF + (((uint32_t)((kk - 8) * 16) + arow) * SROW) * 2;
                    base_lo = sb + A2_OFF + (((uint32_t)(32 + (kk - 8) * 16) + arow) * SROW) * 2;
                }
                ldsm4t(ah0, base_hi + acol * 2);
                ldsm4t(ah1, base_hi + (acol + 16) * 2);
                ldsm4t(al0, base_lo + acol * 2);
                ldsm4t(al1, base_lo + (acol + 16) * 2);
#pragma unroll
                for (int nj = 0; nj < 2; nj++) {
                    uint32_t b[4];
                    ldsm4(b, sb + B2_OFF + ((brow2 + nj * 16) * SB2 + (uint32_t)(kk * 16) + bcol8) * 2);
                    mma16816h(acc2[0][2 * nj], ah0, b[0], b[1]);
                    mma16816h(acc2[0][2 * nj + 1], ah0, b[2], b[3]);
                    mma16816h(acc2[1][2 * nj], ah1, b[0], b[1]);
                    mma16816h(acc2[1][2 * nj + 1], ah1, b[2], b[3]);
                    mma16816h(acc2[0][2 * nj], al0, b[0], b[1]);
                    mma16816h(acc2[0][2 * nj + 1], al0, b[2], b[3]);
                    mma16816h(acc2[1][2 * nj], al1, b[0], b[1]);
                    mma16816h(acc2[1][2 * nj + 1], al1, b[2], b[3]);
                }
            }
        } else if (t + 1 < TSTEPS) {
            // warps 8-15: prefetch x(t+1) into A1 rows 0-15 / 144-159
            for (int task = tid - 256; task < 512; task += 256) {
                const int part = task >> 8, f = (task >> 4) & 15, mg = task & 15;
                const __half* src = (part ? g_actlo : g_acthi)
                                    + (size_t)((t + 1) * FEAT + f) * BATCH + m0 + mg * 8;
                cp16(sb + A1_OFF + (uint32_t)((part * 144 + f) * SROW + mg * 8) * 2, src);
            }
            CP_COMMIT();
        }
        CLUSTER_SYNC();   // (3) A2/A1 reads for lstm2 done (both CTAs)

        if (wid < 8) {
            // ---- epilogue2: gates -> c2 gmem, h2 -> local + peer smem ----
#pragma unroll
            for (int ni = 0; ni < 4; ni++) {
                const int u = (((int)rank * 64 + wn2 * 32 + ni * 8) >> 2) + ((lane & 2) >> 1);
                const float4 bb = *(const float4*)(g_bc2 + 4 * u);
#pragma unroll
                for (int mi = 0; mi < 2; mi++) {
                    const float d0 = acc2[mi][ni][0], d1 = acc2[mi][ni][1];
                    const float d2 = acc2[mi][ni][2], d3 = acc2[mi][ni][3];
                    const float s0 = __shfl_xor_sync(0xffffffffu, odd ? d0 : d2, 1);
                    const float s1 = __shfl_xor_sync(0xffffffffu, odd ? d1 : d3, 1);
                    const float zi = (odd ? s0 : d0) + bb.x;
                    const float zf = (odd ? s1 : d1) + bb.y;
                    const float zg = (odd ? d2 : s0) + bb.z;
                    const float zo = (odd ? d3 : s1) + bb.w;
                    const int row_l = wm * 32 + mi * 16 + g + (odd ? 8 : 0);
                    const float ig = fsigm(zi);
                    const float fg = fsigm(zf);
                    const float gg = ftanh(zg);
                    const float og = fsigm(zo);
                    const size_t coff = (size_t)u * BATCH + m0 + row_l;
                    const float cn = fg * g_c2[coff] + ig * gg;
                    g_c2[coff] = cn;
                    const float hv = og * ftanh(cn);
                    const __half hh = __float2half_rn(hv);
                    const __half hl = __float2half_rn(hv - __half2float(hh));
                    const uint32_t ohi = (uint32_t)(u * SROW + row_l);
                    const uint32_t olo = (uint32_t)((32 + u) * SROW + row_l);
                    A2h[ohi] = hh;
                    A2h[olo] = hl;
                    st_peer16(sb + A2_OFF + ohi * 2, peer, __half_as_ushort(hh));
                    st_peer16(sb + A2_OFF + olo * 2, peer, __half_as_ushort(hl));
                    if (t == TSTEPS - 1) {
                        g_h2fhi[coff] = hh;
                        g_h2flo[coff] = hl;
                    }
                }
            }
        } else {
            CP_WAIT(0);   // x(t+1) landed before the barrier
        }
        CLUSTER_SYNC();   // (4) h2 visible; x(t+1) ready
    }
}

// ---------------- init & prepack ----------------
__global__ void init_state_kernel() {
    int idx = blockIdx.x * blockDim.x + threadIdx.x;
    int stride = gridDim.x * blockDim.x;
    for (int i = idx; i < BATCH * H1; i += stride) g_c1[i] = 0.f;
    for (int i = idx; i < BATCH * H2; i += stride) g_c2[i] = 0.f;
}

__global__ void prepack_kernel(const float* __restrict__ Wx1, const float* __restrict__ Wh1,
                               const float* __restrict__ b1,
                               const float* __restrict__ Wx2, const float* __restrict__ Wh2,
                               const float* __restrict__ b2,
                               const float* __restrict__ W_d1, const float* __restrict__ b_d1,
                               const float* __restrict__ gamma, const float* __restrict__ beta,
                               const float* __restrict__ mean, const float* __restrict__ var) {
    int idx = blockIdx.x * blockDim.x + threadIdx.x;
    int stride = gridDim.x * blockDim.x;
    {
        constexpr int K = FEAT + H1;
        for (int i = idx; i < 4 * H1 * K; i += stride) {
            int n = i / K, k = i % K;
            int u = n >> 2, g = n & 3, src = g * H1 + u;
            float w = (k < FEAT) ? Wx1[k * 4 * H1 + src] : Wh1[(k - FEAT) * 4 * H1 + src];
            g_Wp1[(size_t)n * K + k] = __float2half_rn(w);
        }
        for (int i = idx; i < 4 * H1; i += stride) {
            int u = i >> 2, g = i & 3;
            g_bc1[i] = b1[g * H1 + u];
        }
    }
    {
        constexpr int K = H1 + H2;
        for (int i = idx; i < 4 * H2 * K; i += stride) {
            int n = i / K, k = i % K;
            int u = n >> 2, g = n & 3, src = g * H2 + u;
            float w = (k < H1) ? Wx2[k * 4 * H2 + src] : Wh2[(k - H1) * 4 * H2 + src];
            g_Wp2[(size_t)n * K + k] = __float2half_rn(w);
        }
        for (int i = idx; i < 4 * H2; i += stride) {
            int u = i >> 2, g = i & 3;
            g_bc2[i] = b2[g * H2 + u];
        }
    }
    for (int i = idx; i < D_DENSE * D_IN; i += stride) {
        int n = i / D_IN, k = i % D_IN;
        int p = k >> 7, kk = k & 127;
        float w = W_d1[(size_t)k * D_DENSE + n];
        __nv_bfloat16 hi = __float2bfloat16(w);
        g_WpD[(size_t)n * 1024 + p * 256 + kk] = hi;
        g_WpD[(size_t)n * 1024 + p * 256 + 128 + kk] = __float2bfloat16(w - __bfloat162float(hi));
    }
    for (int i = idx; i < D_DENSE; i += stride) {
        float sc = gamma[i] * rsqrtf(var[i] + 1e-3f);
        g_d1sc[i] = sc;
        g_d1sh[i] = beta[i] + (b_d1[i] - mean[i]) * sc;
    }
}

// ---------------- Dense1 (verified bf16 3-term engine), act col-major fp16 ----------------
template <int K, int S>
__device__ __forceinline__ void warp_gemm3(uint32_t Asm, uint32_t Bsm,
                                           int wm, int wn, int lane, float acc[2][8][4]) {
    const uint32_t abase = Asm + ((((uint32_t)(wm * 32 + (lane & 15))) * S + ((lane >> 4) << 3)) << 1);
    const uint32_t bbase = Bsm + ((((uint32_t)(wn * 64 + ((lane >> 4) << 3) + (lane & 7))) * S
                                   + (((lane >> 3) & 1) << 3)) << 1);
#pragma unroll
    for (int term = 0; term < 3; term++) {
        const int ao = (term == 1) ? K : 0;
        const int bo = (term == 2) ? K : 0;
#pragma unroll
        for (int c = 0; c < K / 16; c++) {
            uint32_t a0[4], a1[4], b[4][4];
            ldsm4(a0, abase + ((ao + c * 16) << 1));
            ldsm4(a1, abase + ((16 * S + ao + c * 16) << 1));
#pragma unroll
            for (int nj = 0; nj < 4; nj++)
                ldsm4(b[nj], bbase + (((nj * 16) * S + bo + c * 16) << 1));
#pragma unroll
            for (int mi = 0; mi < 2; mi++) {
                const uint32_t* A = mi ? a1 : a0;
#pragma unroll
                for (int nj = 0; nj < 4; nj++) {
                    mma16816bf(acc[mi][2 * nj], A, b[nj][0], b[nj][1]);
                    mma16816bf(acc[mi][2 * nj + 1], A, b[nj][2], b[nj][3]);
                }
            }
        }
    }
}

__global__ __launch_bounds__(256, 1) void dense1_kernel(const float* __restrict__ x) {
    constexpr int KP = 128;
    constexpr int S = 2 * KP + 8;    // 264
    extern __shared__ char smem[];
    const uint32_t Asm = smem_u32(smem);
    const uint32_t Bsm = Asm + 128 * S * 2;
    char* const Bc = smem + 128 * S * 2;
    const int tid = threadIdx.x;
    const int lane = tid & 31, wid = tid >> 5;
    const int wm = wid & 3, wn = wid >> 2;
    const int m0 = blockIdx.x * 128, n0 = blockIdx.y * 128;

    float acc[2][8][4] = {};
    for (int p = 0; p < 4; p++) {
        for (int task = tid; task < 128 * 16; task += 256) {
            const int r = task >> 4, o = task & 15;
            const float* src = x + (size_t)(m0 + r) * D_IN + p * KP + o * 8;
            const float4 v0 = *(const float4*)src;
            const float4 v1 = *(const float4*)(src + 4);
            __nv_bfloat16 h[8], l[8];
            const float vv[8] = {v0.x, v0.y, v0.z, v0.w, v1.x, v1.y, v1.z, v1.w};
#pragma unroll
            for (int i = 0; i < 8; i++) {
                h[i] = __float2bfloat16(vv[i]);
                l[i] = __float2bfloat16(vv[i] - __bfloat162float(h[i]));
            }
            *(uint4*)(smem + ((size_t)r * S + o * 8) * 2) = *(uint4*)h;
            *(uint4*)(smem + ((size_t)r * S + KP + o * 8) * 2) = *(uint4*)l;
        }
        for (int task = tid; task < 128 * 32; task += 256) {
            const int n = task >> 5, o = task & 31;
            const uint4 v = *(const uint4*)(g_WpD + (size_t)(n0 + n) * 1024 + p * 256 + o * 8);
            *(uint4*)(Bc + ((size_t)n * S + o * 8) * 2) = v;
        }
        __syncthreads();
        warp_gemm3<KP, S>(Asm, Bsm, wm, wn, lane, acc);
        __syncthreads();
    }

    const int g = lane >> 2;
#pragma unroll
    for (int ni = 0; ni < 8; ni++) {
        const int n = n0 + wn * 64 + ni * 8 + (lane & 3) * 2;
        const float sc0 = g_d1sc[n], sc1 = g_d1sc[n + 1];
        const float sh0 = g_d1sh[n], sh1 = g_d1sh[n + 1];
#pragma unroll
        for (int mi = 0; mi < 2; mi++) {
#pragma unroll
            for (int half = 0; half < 2; half++) {
                const int row = m0 + wm * 32 + mi * 16 + g + half * 8;
                float v0 = acc[mi][ni][half * 2 + 0] * sc0 + sh0;
                float v1 = acc[mi][ni][half * 2 + 1] * sc1 + sh1;
                v0 = (v0 >= 0.f) ? v0 : 0.2f * v0;
                v1 = (v1 >= 0.f) ? v1 : 0.2f * v1;
                const __half h0 = __float2half_rn(v0), h1 = __float2half_rn(v1);
                g_acthi[(size_t)n * BATCH + row] = h0;
                g_acthi[(size_t)(n + 1) * BATCH + row] = h1;
                g_actlo[(size_t)n * BATCH + row] = __float2half_rn(v0 - __half2float(h0));
                g_actlo[(size_t)(n + 1) * BATCH + row] = __float2half_rn(v1 - __half2float(h1));
            }
        }
    }
}

// ---------------- Dense2 + softmax ----------------
__global__ __launch_bounds__(256) void dense2_softmax_kernel(
    const float* __restrict__ Wd2, const float* __restrict__ bd2, float* __restrict__ out) {
    __shared__ float Ws[H2 * NCLS];
    __shared__ float bs[NCLS];
    int tid = threadIdx.x;
    for (int i = tid; i < H2 * NCLS; i += blockDim.x) Ws[i] = Wd2[i];
    if (tid < NCLS) bs[tid] = bd2[tid];
    __syncthreads();
    int row = blockIdx.x * blockDim.x + tid;
    float acc[NCLS];
#pragma unroll
    for (int j = 0; j < NCLS; j++) acc[j] = bs[j];
#pragma unroll
    for (int k = 0; k < H2; k++) {
        float xv = __half2float(g_h2fhi[(size_t)k * BATCH + row])
                 + __half2float(g_h2flo[(size_t)k * BATCH + row]);
#pragma unroll
        for (int j = 0; j < NCLS; j++) acc[j] += xv * Ws[k * NCLS + j];
    }
    float m = acc[0];
#pragma unroll
    for (int j = 1; j < NCLS; j++) m = fmaxf(m, acc[j]);
    float ssum = 0.f;
#pragma unroll
    for (int j = 0; j < NCLS; j++) { acc[j] = expf(acc[j] - m); ssum += acc[j]; }
    float inv = 1.f / ssum;
#pragma unroll
    for (int j = 0; j < NCLS; j++) out[(size_t)row * NCLS + j] = acc[j] * inv;
}

// ---------------- launch ----------------
extern "C" void kernel_launch(void* const* d_in, const int* in_sizes, int n_in,
                              void* d_out, int out_size) {
    const float* x        = (const float*)d_in[0];
    const float* W_d1     = (const float*)d_in[1];
    const float* b_d1     = (const float*)d_in[2];
    const float* bn_gamma = (const float*)d_in[3];
    const float* bn_beta  = (const float*)d_in[4];
    const float* bn_mean  = (const float*)d_in[5];
    const float* bn_var   = (const float*)d_in[6];
    const float* Wx1      = (const float*)d_in[7];
    const float* Wh1      = (const float*)d_in[8];
    const float* b1       = (const float*)d_in[9];
    const float* Wx2      = (const float*)d_in[10];
    const float* Wh2      = (const float*)d_in[11];
    const float* b2       = (const float*)d_in[12];
    const float* W_d2     = (const float*)d_in[13];
    const float* b_d2     = (const float*)d_in[14];
    float* out = (float*)d_out;

    const int SMD = 2 * 128 * (2 * 128 + 8) * 2;   // 135168

    cudaFuncSetAttribute(dense1_kernel, cudaFuncAttributeMaxDynamicSharedMemorySize, SMD);
    cudaFuncSetAttribute(rnn_kernel, cudaFuncAttributeMaxDynamicSharedMemorySize, SMEM_RNN);

    prepack_kernel<<<256, 256>>>(Wx1, Wh1, b1, Wx2, Wh2, b2, W_d1, b_d1,
                                 bn_gamma, bn_beta, bn_mean, bn_var);
    init_state_kernel<<<2048, 256>>>();
    dense1_kernel<<<dim3(BATCH / 128, D_DENSE / 128), 256, SMD>>>(x);
    rnn_kernel<<<512, 512, SMEM_RNN>>>();
    dense2_softmax_kernel<<<BATCH / 256, 256>>>(W_d2, b_d2, out);
}

// round 12
// speedup vs baseline: 1.3620x; 1.3620x over previous
#include <cuda_runtime.h>
#include <cuda_bf16.h>
#include <cuda_fp16.h>
#include <math.h>
#include <stdint.h>

#define BATCH   32768
#define D_IN    512
#define D_DENSE 256
#define TSTEPS  16
#define FEAT    16
#define H1      128
#define H2      32
#define NCLS    10

// ---------------- state: COLUMN-major [feature][BATCH], single fp16 ----------------
__device__ __half g_act[D_DENSE * BATCH];
__device__ __half g_h1[2][H1 * BATCH];
__device__ __half g_h2[2][H2 * BATCH];
__device__ float g_c1[H1 * BATCH], g_c2[H2 * BATCH];

// prepacked LSTM weights: single fp16, row n (gate-interleaved), K cols
__device__ __half g_Wp1[(4 * H1) * (FEAT + H1)];   // [512][144]
__device__ __half g_Wp2[(4 * H2) * (H1 + H2)];     // [128][160]
// dense1 weights: bf16 hi/lo 3-term (verified engine)
__device__ __nv_bfloat16 g_WpD[D_DENSE * 2 * D_IN];
__device__ float g_bc1[4 * H1], g_bc2[4 * H2];
__device__ float g_d1sc[D_DENSE], g_d1sh[D_DENSE];

// ---------------- helpers ----------------
__device__ __forceinline__ uint32_t smem_u32(const void* p) {
    uint32_t a;
    asm("{ .reg .u64 t; cvta.to.shared.u64 t, %1; cvt.u32.u64 %0, t; }" : "=r"(a) : "l"(p));
    return a;
}
__device__ __forceinline__ float ftanh(float x) {
    float y;
    asm("tanh.approx.f32 %0, %1;" : "=f"(y) : "f"(x));
    return y;
}
__device__ __forceinline__ float fsigm(float x) { return 0.5f * ftanh(0.5f * x) + 0.5f; }

__device__ __forceinline__ void ldsm4(uint32_t* r, uint32_t addr) {
    asm volatile("ldmatrix.sync.aligned.m8n8.x4.shared.b16 {%0,%1,%2,%3}, [%4];"
                 : "=r"(r[0]), "=r"(r[1]), "=r"(r[2]), "=r"(r[3]) : "r"(addr));
}
__device__ __forceinline__ void ldsm4t(uint32_t* r, uint32_t addr) {
    asm volatile("ldmatrix.sync.aligned.m8n8.x4.trans.shared.b16 {%0,%1,%2,%3}, [%4];"
                 : "=r"(r[0]), "=r"(r[1]), "=r"(r[2]), "=r"(r[3]) : "r"(addr));
}
__device__ __forceinline__ void mma16816bf(float* d, const uint32_t* a, uint32_t b0, uint32_t b1) {
    asm volatile(
        "mma.sync.aligned.m16n8k16.row.col.f32.bf16.bf16.f32 "
        "{%0,%1,%2,%3}, {%4,%5,%6,%7}, {%8,%9}, {%0,%1,%2,%3};"
        : "+f"(d[0]), "+f"(d[1]), "+f"(d[2]), "+f"(d[3])
        : "r"(a[0]), "r"(a[1]), "r"(a[2]), "r"(a[3]), "r"(b0), "r"(b1));
}
__device__ __forceinline__ void mma16816h(float* d, const uint32_t* a, uint32_t b0, uint32_t b1) {
    asm volatile(
        "mma.sync.aligned.m16n8k16.row.col.f32.f16.f16.f32 "
        "{%0,%1,%2,%3}, {%4,%5,%6,%7}, {%8,%9}, {%0,%1,%2,%3};"
        : "+f"(d[0]), "+f"(d[1]), "+f"(d[2]), "+f"(d[3])
        : "r"(a[0]), "r"(a[1]), "r"(a[2]), "r"(a[3]), "r"(b0), "r"(b1));
}
__device__ __forceinline__ void cp16(uint32_t dst, const void* src) {
    asm volatile("cp.async.cg.shared.global [%0], [%1], 16;" :: "r"(dst), "l"(src));
}
#define CP_COMMIT() asm volatile("cp.async.commit_group;" ::: "memory")
#define CP_WAIT(n)  asm volatile("cp.async.wait_group %0;" :: "n"(n) : "memory")

// ===== fused LSTM step: single fp16, ONE-SHOT load (no chunking), resident B =====
// 256 threads, 8 warps 4(M)x2(N), warp tile 32x64, CTA tile 128x128.
template <int KX, int HID>
__device__ __forceinline__ void lstm_body(int t, int m0, int n0, char* smemc) {
    constexpr int K = KX + HID;
    constexpr int SROW = 136;                 // A smem: elems per k-row (272B, conflict-free)
    constexpr int SB = K + 8;                 // B row length in halfs (row bytes /16 odd)
    constexpr int GB = K / 8;
    const int tid = threadIdx.x;
    const int lane = tid & 31, wid = tid >> 5;
    const int wm = wid & 3, wn = wid >> 2;    // 4 x 2
    const uint32_t sbase = smem_u32(smemc);
    const uint32_t Bbase = sbase + (uint32_t)(K * SROW * 2);
    const int p = t & 1;

    const __half *xsrc, *hsrc;
    __half* hdst;
    float* cbuf;
    const __half* W;
    const float* bias;
    int xoff;
    if (HID == H1) {
        xsrc = g_act; xoff = t * FEAT;
        hsrc = g_h1[p]; hdst = g_h1[p ^ 1];
        cbuf = g_c1; W = g_Wp1; bias = g_bc1;
    } else {
        xsrc = g_h1[p ^ 1]; xoff = 0;
        hsrc = g_h2[p]; hdst = g_h2[p ^ 1];
        cbuf = g_c2; W = g_Wp2; bias = g_bc2;
    }

    // one-shot load: full A (K x 128) + resident B, single group
#pragma unroll
    for (int task = tid; task < K * 16; task += 256) {
        const int k = task >> 4, mg = task & 15;
        const __half* src = (k < KX)
            ? xsrc + (size_t)(xoff + k) * BATCH + m0 + mg * 8
            : hsrc + (size_t)(k - KX) * BATCH + m0 + mg * 8;
        cp16(sbase + (uint32_t)(k * SROW + mg * 8) * 2, src);
    }
#pragma unroll
    for (int task = tid; task < 128 * GB; task += 256) {
        const int n = task / GB, gg = task % GB;
        cp16(Bbase + (uint32_t)(n * SB + gg * 8) * 2,
             W + (size_t)(n0 + n) * K + gg * 8);
    }
    CP_COMMIT();
    CP_WAIT(0);
    __syncthreads();

    const uint32_t arow = (uint32_t)((lane & 7) + ((lane >> 4) << 3));
    const uint32_t acol = (uint32_t)(wm * 32 + (((lane >> 3) & 1) << 3));
    const uint32_t brow = (uint32_t)(wn * 64 + ((lane >> 4) << 3) + (lane & 7));
    const uint32_t bcol8 = (uint32_t)(((lane >> 3) & 1) << 3);
    float acc[2][8][4] = {};

#pragma unroll
    for (int kk = 0; kk < K / 16; kk++) {
        uint32_t a0[4], a1[4];
        const uint32_t hr = (uint32_t)(kk * 16) + arow;
        ldsm4t(a0, sbase + (hr * SROW + acol) * 2);
        ldsm4t(a1, sbase + (hr * SROW + acol + 16) * 2);
        const uint32_t cofs = (uint32_t)(kk * 16) + bcol8;
#pragma unroll
        for (int nj = 0; nj < 4; nj++) {
            uint32_t b[4];
            ldsm4(b, Bbase + ((brow + nj * 16) * SB + cofs) * 2);
            mma16816h(acc[0][2 * nj], a0, b[0], b[1]);
            mma16816h(acc[0][2 * nj + 1], a0, b[2], b[3]);
            mma16816h(acc[1][2 * nj], a1, b[0], b[1]);
            mma16816h(acc[1][2 * nj + 1], a1, b[2], b[3]);
        }
    }

    // epilogue: pair-swap gates; col-major fp16 state -> coalesced stores
    const int g = lane >> 2;
    const bool odd = lane & 1;
#pragma unroll
    for (int ni = 0; ni < 8; ni++) {
        const int u = ((n0 + wn * 64 + ni * 8) >> 2) + ((lane & 2) >> 1);
        const float4 bb = *(const float4*)(bias + 4 * u);
#pragma unroll
        for (int mi = 0; mi < 2; mi++) {
            const float d0 = acc[mi][ni][0], d1 = acc[mi][ni][1];
            const float d2 = acc[mi][ni][2], d3 = acc[mi][ni][3];
            const float s0 = __shfl_xor_sync(0xffffffffu, odd ? d0 : d2, 1);
            const float s1 = __shfl_xor_sync(0xffffffffu, odd ? d1 : d3, 1);
            const float zi = (odd ? s0 : d0) + bb.x;
            const float zf = (odd ? s1 : d1) + bb.y;
            const float zg = (odd ? d2 : s0) + bb.z;
            const float zo = (odd ? d3 : s1) + bb.w;
            const int row = m0 + wm * 32 + mi * 16 + g + (odd ? 8 : 0);
            const float ig = fsigm(zi);
            const float fg = fsigm(zf);
            const float gg = ftanh(zg);
            const float og = fsigm(zo);
            const size_t off = (size_t)u * BATCH + row;   // col-major
            const float cn = fg * cbuf[off] + ig * gg;
            cbuf[off] = cn;
            hdst[off] = __float2half_rn(og * ftanh(cn));
        }
    }
}

__global__ __launch_bounds__(256, 2) void lstm1_first_kernel() {
    extern __shared__ char smem[];
    lstm_body<FEAT, H1>(0, (blockIdx.x & 255) * 128, (blockIdx.x >> 8) * 128, smem);
}

// combined: lstm2(t) on blocks [0,256); lstm1(t+1) on blocks [256,1280)
__global__ __launch_bounds__(256, 2) void step_kernel(int t, int do_l1) {
    extern __shared__ char smem[];
    if (blockIdx.x < 256) {
        lstm_body<H1, H2>(t, blockIdx.x * 128, 0, smem);
    } else if (do_l1) {
        const int bx = blockIdx.x - 256;
        lstm_body<FEAT, H1>(t + 1, (bx & 255) * 128, (bx >> 8) * 128, smem);
    }
}

// ---------------- init & prepack ----------------
__global__ void init_state_kernel() {
    int idx = blockIdx.x * blockDim.x + threadIdx.x;
    int stride = gridDim.x * blockDim.x;
    const __half z = __float2half(0.f);
    for (int i = idx; i < BATCH * H1; i += stride) { g_h1[0][i] = z; g_c1[i] = 0.f; }
    for (int i = idx; i < BATCH * H2; i += stride) { g_h2[0][i] = z; g_c2[i] = 0.f; }
}

__global__ void prepack_kernel(const float* __restrict__ Wx1, const float* __restrict__ Wh1,
                               const float* __restrict__ b1,
                               const float* __restrict__ Wx2, const float* __restrict__ Wh2,
                               const float* __restrict__ b2,
                               const float* __restrict__ W_d1, const float* __restrict__ b_d1,
                               const float* __restrict__ gamma, const float* __restrict__ beta,
                               const float* __restrict__ mean, const float* __restrict__ var) {
    int idx = blockIdx.x * blockDim.x + threadIdx.x;
    int stride = gridDim.x * blockDim.x;
    {
        constexpr int K = FEAT + H1;
        for (int i = idx; i < 4 * H1 * K; i += stride) {
            int n = i / K, k = i % K;
            int u = n >> 2, g = n & 3, src = g * H1 + u;
            float w = (k < FEAT) ? Wx1[k * 4 * H1 + src] : Wh1[(k - FEAT) * 4 * H1 + src];
            g_Wp1[(size_t)n * K + k] = __float2half_rn(w);
        }
        for (int i = idx; i < 4 * H1; i += stride) {
            int u = i >> 2, g = i & 3;
            g_bc1[i] = b1[g * H1 + u];
        }
    }
    {
        constexpr int K = H1 + H2;
        for (int i = idx; i < 4 * H2 * K; i += stride) {
            int n = i / K, k = i % K;
            int u = n >> 2, g = n & 3, src = g * H2 + u;
            float w = (k < H1) ? Wx2[k * 4 * H2 + src] : Wh2[(k - H1) * 4 * H2 + src];
            g_Wp2[(size_t)n * K + k] = __float2half_rn(w);
        }
        for (int i = idx; i < 4 * H2; i += stride) {
            int u = i >> 2, g = i & 3;
            g_bc2[i] = b2[g * H2 + u];
        }
    }
    // Dense1 weights: bf16 hi/lo panel-major (verified)
    for (int i = idx; i < D_DENSE * D_IN; i += stride) {
        int n = i / D_IN, k = i % D_IN;
        int p = k >> 7, kk = k & 127;
        float w = W_d1[(size_t)k * D_DENSE + n];
        __nv_bfloat16 hi = __float2bfloat16(w);
        g_WpD[(size_t)n * 1024 + p * 256 + kk] = hi;
        g_WpD[(size_t)n * 1024 + p * 256 + 128 + kk] = __float2bfloat16(w - __bfloat162float(hi));
    }
    for (int i = idx; i < D_DENSE; i += stride) {
        float sc = gamma[i] * rsqrtf(var[i] + 1e-3f);
        g_d1sc[i] = sc;
        g_d1sh[i] = beta[i] + (b_d1[i] - mean[i]) * sc;
    }
}

// ---------------- Dense1 (verified bf16 3-term engine), act col-major single fp16 ---------
template <int K, int S>
__device__ __forceinline__ void warp_gemm3(uint32_t Asm, uint32_t Bsm,
                                           int wm, int wn, int lane, float acc[2][8][4]) {
    const uint32_t abase = Asm + ((((uint32_t)(wm * 32 + (lane & 15))) * S + ((lane >> 4) << 3)) << 1);
    const uint32_t bbase = Bsm + ((((uint32_t)(wn * 64 + ((lane >> 4) << 3) + (lane & 7))) * S
                                   + (((lane >> 3) & 1) << 3)) << 1);
#pragma unroll
    for (int term = 0; term < 3; term++) {
        const int ao = (term == 1) ? K : 0;
        const int bo = (term == 2) ? K : 0;
#pragma unroll
        for (int c = 0; c < K / 16; c++) {
            uint32_t a0[4], a1[4], b[4][4];
            ldsm4(a0, abase + ((ao + c * 16) << 1));
            ldsm4(a1, abase + ((16 * S + ao + c * 16) << 1));
#pragma unroll
            for (int nj = 0; nj < 4; nj++)
                ldsm4(b[nj], bbase + (((nj * 16) * S + bo + c * 16) << 1));
#pragma unroll
            for (int mi = 0; mi < 2; mi++) {
                const uint32_t* A = mi ? a1 : a0;
#pragma unroll
                for (int nj = 0; nj < 4; nj++) {
                    mma16816bf(acc[mi][2 * nj], A, b[nj][0], b[nj][1]);
                    mma16816bf(acc[mi][2 * nj + 1], A, b[nj][2], b[nj][3]);
                }
            }
        }
    }
}

__global__ __launch_bounds__(256, 1) void dense1_kernel(const float* __restrict__ x) {
    constexpr int KP = 128;
    constexpr int S = 2 * KP + 8;    // 264
    extern __shared__ char smem[];
    const uint32_t Asm = smem_u32(smem);
    const uint32_t Bsm = Asm + 128 * S * 2;
    char* const Bc = smem + 128 * S * 2;
    const int tid = threadIdx.x;
    const int lane = tid & 31, wid = tid >> 5;
    const int wm = wid & 3, wn = wid >> 2;
    const int m0 = blockIdx.x * 128, n0 = blockIdx.y * 128;

    float acc[2][8][4] = {};
    for (int p = 0; p < 4; p++) {
        for (int task = tid; task < 128 * 16; task += 256) {
            const int r = task >> 4, o = task & 15;
            const float* src = x + (size_t)(m0 + r) * D_IN + p * KP + o * 8;
            const float4 v0 = *(const float4*)src;
            const float4 v1 = *(const float4*)(src + 4);
            __nv_bfloat16 h[8], l[8];
            const float vv[8] = {v0.x, v0.y, v0.z, v0.w, v1.x, v1.y, v1.z, v1.w};
#pragma unroll
            for (int i = 0; i < 8; i++) {
                h[i] = __float2bfloat16(vv[i]);
                l[i] = __float2bfloat16(vv[i] - __bfloat162float(h[i]));
            }
            *(uint4*)(smem + ((size_t)r * S + o * 8) * 2) = *(uint4*)h;
            *(uint4*)(smem + ((size_t)r * S + KP + o * 8) * 2) = *(uint4*)l;
        }
        for (int task = tid; task < 128 * 32; task += 256) {
            const int n = task >> 5, o = task & 31;
            const uint4 v = *(const uint4*)(g_WpD + (size_t)(n0 + n) * 1024 + p * 256 + o * 8);
            *(uint4*)(Bc + ((size_t)n * S + o * 8) * 2) = v;
        }
        __syncthreads();
        warp_gemm3<KP, S>(Asm, Bsm, wm, wn, lane, acc);
        __syncthreads();
    }

    const int g = lane >> 2;
#pragma unroll
    for (int ni = 0; ni < 8; ni++) {
        const int n = n0 + wn * 64 + ni * 8 + (lane & 3) * 2;
        const float sc0 = g_d1sc[n], sc1 = g_d1sc[n + 1];
        const float sh0 = g_d1sh[n], sh1 = g_d1sh[n + 1];
#pragma unroll
        for (int mi = 0; mi < 2; mi++) {
#pragma unroll
            for (int half = 0; half < 2; half++) {
                const int row = m0 + wm * 32 + mi * 16 + g + half * 8;
                float v0 = acc[mi][ni][half * 2 + 0] * sc0 + sh0;
                float v1 = acc[mi][ni][half * 2 + 1] * sc1 + sh1;
                v0 = (v0 >= 0.f) ? v0 : 0.2f * v0;
                v1 = (v1 >= 0.f) ? v1 : 0.2f * v1;
                g_act[(size_t)n * BATCH + row] = __float2half_rn(v0);
                g_act[(size_t)(n + 1) * BATCH + row] = __float2half_rn(v1);
            }
        }
    }
}

// ---------------- Dense2 + softmax (col-major fp16 h2) ----------------
__global__ __launch_bounds__(256) void dense2_softmax_kernel(
    const float* __restrict__ Wd2, const float* __restrict__ bd2, float* __restrict__ out) {
    __shared__ float Ws[H2 * NCLS];
    __shared__ float bs[NCLS];
    int tid = threadIdx.x;
    for (int i = tid; i < H2 * NCLS; i += blockDim.x) Ws[i] = Wd2[i];
    if (tid < NCLS) bs[tid] = bd2[tid];
    __syncthreads();
    int row = blockIdx.x * blockDim.x + tid;
    const __half* hh = g_h2[0];  // t=15 writes buffer 0
    float acc[NCLS];
#pragma unroll
    for (int j = 0; j < NCLS; j++) acc[j] = bs[j];
#pragma unroll
    for (int k = 0; k < H2; k++) {
        float xv = __half2float(hh[(size_t)k * BATCH + row]);
#pragma unroll
        for (int j = 0; j < NCLS; j++) acc[j] += xv * Ws[k * NCLS + j];
    }
    float m = acc[0];
#pragma unroll
    for (int j = 1; j < NCLS; j++) m = fmaxf(m, acc[j]);
    float ssum = 0.f;
#pragma unroll
    for (int j = 0; j < NCLS; j++) { acc[j] = expf(acc[j] - m); ssum += acc[j]; }
    float inv = 1.f / ssum;
#pragma unroll
    for (int j = 0; j < NCLS; j++) out[(size_t)row * NCLS + j] = acc[j] * inv;
}

// ---------------- launch ----------------
extern "C" void kernel_launch(void* const* d_in, const int* in_sizes, int n_in,
                              void* d_out, int out_size) {
    const float* x        = (const float*)d_in[0];
    const float* W_d1     = (const float*)d_in[1];
    const float* b_d1     = (const float*)d_in[2];
    const float* bn_gamma = (const float*)d_in[3];
    const float* bn_beta  = (const float*)d_in[4];
    const float* bn_mean  = (const float*)d_in[5];
    const float* bn_var   = (const float*)d_in[6];
    const float* Wx1      = (const float*)d_in[7];
    const float* Wh1      = (const float*)d_in[8];
    const float* b1       = (const float*)d_in[9];
    const float* Wx2      = (const float*)d_in[10];
    const float* Wh2      = (const float*)d_in[11];
    const float* b2       = (const float*)d_in[12];
    const float* W_d2     = (const float*)d_in[13];
    const float* b_d2     = (const float*)d_in[14];
    float* out = (float*)d_out;

    // LSTM1: 144*136*2 + 128*152*2 = 39168 + 38912 = 78080
    // LSTM2: 160*136*2 + 128*168*2 = 43520 + 43008 = 86528
    const int SM_STEP = 86528;
    const int SMD     = 2 * 128 * (2 * 128 + 8) * 2;     // 135168

    cudaFuncSetAttribute(dense1_kernel, cudaFuncAttributeMaxDynamicSharedMemorySize, SMD);
    cudaFuncSetAttribute(lstm1_first_kernel, cudaFuncAttributeMaxDynamicSharedMemorySize, SM_STEP);
    cudaFuncSetAttribute(step_kernel, cudaFuncAttributeMaxDynamicSharedMemorySize, SM_STEP);

    prepack_kernel<<<256, 256>>>(Wx1, Wh1, b1, Wx2, Wh2, b2, W_d1, b_d1,
                                 bn_gamma, bn_beta, bn_mean, bn_var);
    init_state_kernel<<<2048, 256>>>();
    dense1_kernel<<<dim3(BATCH / 128, D_DENSE / 128), 256, SMD>>>(x);
    lstm1_first_kernel<<<1024, 256, SM_STEP>>>();
    for (int t = 0; t < TSTEPS; t++) {
        step_kernel<<<1280, 256, SM_STEP>>>(t, (t < TSTEPS - 1) ? 1 : 0);
    }
    dense2_softmax_kernel<<<BATCH / 256, 256>>>(W_d2, b_d2, out);
}

// round 13
// speedup vs baseline: 1.4094x; 1.0348x over previous
#include <cuda_runtime.h>
#include <cuda_bf16.h>
#include <cuda_fp16.h>
#include <math.h>
#include <stdint.h>

#define BATCH   32768
#define D_IN    512
#define D_DENSE 256
#define TSTEPS  16
#define FEAT    16
#define H1      128
#define H2      32
#define NCLS    10

// ---------------- state: COLUMN-major [feature][BATCH], single fp16 ----------------
__device__ __half g_act[D_DENSE * BATCH];
__device__ __half g_h1[2][H1 * BATCH];
__device__ __half g_h2[2][H2 * BATCH];
__device__ float g_c1[H1 * BATCH], g_c2[H2 * BATCH];

// prepacked LSTM weights: single fp16, row n (gate-interleaved), K cols
__device__ __half g_Wp1[(4 * H1) * (FEAT + H1)];   // [512][144]
__device__ __half g_Wp2[(4 * H2) * (H1 + H2)];     // [128][160]
// dense1 weights: bf16 hi/lo 3-term (verified engine)
__device__ __nv_bfloat16 g_WpD[D_DENSE * 2 * D_IN];
__device__ float g_bc1[4 * H1], g_bc2[4 * H2];
__device__ float g_d1sc[D_DENSE], g_d1sh[D_DENSE];

// ---------------- helpers ----------------
__device__ __forceinline__ uint32_t smem_u32(const void* p) {
    uint32_t a;
    asm("{ .reg .u64 t; cvta.to.shared.u64 t, %1; cvt.u32.u64 %0, t; }" : "=r"(a) : "l"(p));
    return a;
}
__device__ __forceinline__ float ftanh(float x) {
    float y;
    asm("tanh.approx.f32 %0, %1;" : "=f"(y) : "f"(x));
    return y;
}
__device__ __forceinline__ float fsigm(float x) { return 0.5f * ftanh(0.5f * x) + 0.5f; }

__device__ __forceinline__ void ldsm4(uint32_t* r, uint32_t addr) {
    asm volatile("ldmatrix.sync.aligned.m8n8.x4.shared.b16 {%0,%1,%2,%3}, [%4];"
                 : "=r"(r[0]), "=r"(r[1]), "=r"(r[2]), "=r"(r[3]) : "r"(addr));
}
__device__ __forceinline__ void ldsm4t(uint32_t* r, uint32_t addr) {
    asm volatile("ldmatrix.sync.aligned.m8n8.x4.trans.shared.b16 {%0,%1,%2,%3}, [%4];"
                 : "=r"(r[0]), "=r"(r[1]), "=r"(r[2]), "=r"(r[3]) : "r"(addr));
}
__device__ __forceinline__ void mma16816bf(float* d, const uint32_t* a, uint32_t b0, uint32_t b1) {
    asm volatile(
        "mma.sync.aligned.m16n8k16.row.col.f32.bf16.bf16.f32 "
        "{%0,%1,%2,%3}, {%4,%5,%6,%7}, {%8,%9}, {%0,%1,%2,%3};"
        : "+f"(d[0]), "+f"(d[1]), "+f"(d[2]), "+f"(d[3])
        : "r"(a[0]), "r"(a[1]), "r"(a[2]), "r"(a[3]), "r"(b0), "r"(b1));
}
__device__ __forceinline__ void mma16816h(float* d, const uint32_t* a, uint32_t b0, uint32_t b1) {
    asm volatile(
        "mma.sync.aligned.m16n8k16.row.col.f32.f16.f16.f32 "
        "{%0,%1,%2,%3}, {%4,%5,%6,%7}, {%8,%9}, {%0,%1,%2,%3};"
        : "+f"(d[0]), "+f"(d[1]), "+f"(d[2]), "+f"(d[3])
        : "r"(a[0]), "r"(a[1]), "r"(a[2]), "r"(a[3]), "r"(b0), "r"(b1));
}
__device__ __forceinline__ void cp16(uint32_t dst, const void* src) {
    asm volatile("cp.async.cg.shared.global [%0], [%1], 16;" :: "r"(dst), "l"(src));
}
#define CP_COMMIT() asm volatile("cp.async.commit_group;" ::: "memory")
#define CP_WAIT(n)  asm volatile("cp.async.wait_group %0;" :: "n"(n) : "memory")

// ===== fused LSTM step: single fp16, 2-chunk K-split pipeline (A+B per chunk) =====
// 256 threads, 8 warps 4(M)x2(N), warp tile 32x64, CTA tile 128x128.
#define SROW 136
#define SBC  88
#define ASTG (80 * SROW * 2)         // stage A capacity (max chunk = 80 rows)
#define BSTG (128 * SBC * 2)
#define STG  (ASTG + BSTG)           // 44288
#define SM_STEP (2 * STG)            // 88576

template <int KX, int HID, int BK0>
__device__ __forceinline__ void lstm_body(int t, int m0, int n0, char* smemc) {
    constexpr int K = KX + HID;
    constexpr int BK1 = K - BK0;
    const int tid = threadIdx.x;
    const int lane = tid & 31, wid = tid >> 5;
    const int wm = wid & 3, wn = wid >> 2;    // 4 x 2
    const uint32_t sbase = smem_u32(smemc);
    const int p = t & 1;

    const __half *xsrc, *hsrc;
    __half* hdst;
    float* cbuf;
    const __half* W;
    const float* bias;
    int xoff;
    if (HID == H1) {
        xsrc = g_act; xoff = t * FEAT;
        hsrc = g_h1[p]; hdst = g_h1[p ^ 1];
        cbuf = g_c1; W = g_Wp1; bias = g_bc1;
    } else {
        xsrc = g_h1[p ^ 1]; xoff = 0;
        hsrc = g_h2[p]; hdst = g_h2[p ^ 1];
        cbuf = g_c2; W = g_Wp2; bias = g_bc2;
    }

    // ---- chunk 0 load: A cols [0,BK0), B cols [0,BK0) ----
    {
        const uint32_t As = sbase, Bs = sbase + ASTG;
#pragma unroll
        for (int task = tid; task < BK0 * 16; task += 256) {
            const int k = task >> 4, mg = task & 15;
            const __half* src = (k < KX)
                ? xsrc + (size_t)(xoff + k) * BATCH + m0 + mg * 8
                : hsrc + (size_t)(k - KX) * BATCH + m0 + mg * 8;
            cp16(As + (uint32_t)(k * SROW + mg * 8) * 2, src);
        }
#pragma unroll
        for (int task = tid; task < 128 * (BK0 / 8); task += 256) {
            const int n = task / (BK0 / 8), gg = task % (BK0 / 8);
            cp16(Bs + (uint32_t)(n * SBC + gg * 8) * 2,
                 W + (size_t)(n0 + n) * K + gg * 8);
        }
    }
    CP_COMMIT();
    // ---- chunk 1 load: A cols [BK0,K), B cols [BK0,K) ----
    {
        const uint32_t As = sbase + STG, Bs = sbase + STG + ASTG;
#pragma unroll
        for (int task = tid; task < BK1 * 16; task += 256) {
            const int k = task >> 4, mg = task & 15;
            const int col = BK0 + k;
            const __half* src = (col < KX)
                ? xsrc + (size_t)(xoff + col) * BATCH + m0 + mg * 8
                : hsrc + (size_t)(col - KX) * BATCH + m0 + mg * 8;
            cp16(As + (uint32_t)(k * SROW + mg * 8) * 2, src);
        }
#pragma unroll
        for (int task = tid; task < 128 * (BK1 / 8); task += 256) {
            const int n = task / (BK1 / 8), gg = task % (BK1 / 8);
            cp16(Bs + (uint32_t)(n * SBC + gg * 8) * 2,
                 W + (size_t)(n0 + n) * K + BK0 + gg * 8);
        }
    }
    CP_COMMIT();

    const uint32_t arow = (uint32_t)((lane & 7) + ((lane >> 4) << 3));
    const uint32_t acol = (uint32_t)(wm * 32 + (((lane >> 3) & 1) << 3));
    const uint32_t brow = (uint32_t)(wn * 64 + ((lane >> 4) << 3) + (lane & 7));
    const uint32_t bcol8 = (uint32_t)(((lane >> 3) & 1) << 3);
    float acc[2][8][4] = {};

    // ---- compute chunk 0 (chunk 1 load in flight) ----
    CP_WAIT(1);
    __syncthreads();
#pragma unroll
    for (int kk = 0; kk < BK0 / 16; kk++) {
        uint32_t a0[4], a1[4];
        const uint32_t hr = (uint32_t)(kk * 16) + arow;
        ldsm4t(a0, sbase + (hr * SROW + acol) * 2);
        ldsm4t(a1, sbase + (hr * SROW + acol + 16) * 2);
        const uint32_t cofs = (uint32_t)(kk * 16) + bcol8;
#pragma unroll
        for (int nj = 0; nj < 4; nj++) {
            uint32_t b[4];
            ldsm4(b, sbase + ASTG + ((brow + nj * 16) * SBC + cofs) * 2);
            mma16816h(acc[0][2 * nj], a0, b[0], b[1]);
            mma16816h(acc[0][2 * nj + 1], a0, b[2], b[3]);
            mma16816h(acc[1][2 * nj], a1, b[0], b[1]);
            mma16816h(acc[1][2 * nj + 1], a1, b[2], b[3]);
        }
    }
    // ---- compute chunk 1 ----
    CP_WAIT(0);
    __syncthreads();
#pragma unroll
    for (int kk = 0; kk < BK1 / 16; kk++) {
        uint32_t a0[4], a1[4];
        const uint32_t hr = (uint32_t)(kk * 16) + arow;
        ldsm4t(a0, sbase + STG + (hr * SROW + acol) * 2);
        ldsm4t(a1, sbase + STG + (hr * SROW + acol + 16) * 2);
        const uint32_t cofs = (uint32_t)(kk * 16) + bcol8;
#pragma unroll
        for (int nj = 0; nj < 4; nj++) {
            uint32_t b[4];
            ldsm4(b, sbase + STG + ASTG + ((brow + nj * 16) * SBC + cofs) * 2);
            mma16816h(acc[0][2 * nj], a0, b[0], b[1]);
            mma16816h(acc[0][2 * nj + 1], a0, b[2], b[3]);
            mma16816h(acc[1][2 * nj], a1, b[0], b[1]);
            mma16816h(acc[1][2 * nj + 1], a1, b[2], b[3]);
        }
    }

    // epilogue: pair-swap gates; col-major fp16 state -> coalesced stores
    const int g = lane >> 2;
    const bool odd = lane & 1;
#pragma unroll
    for (int ni = 0; ni < 8; ni++) {
        const int u = ((n0 + wn * 64 + ni * 8) >> 2) + ((lane & 2) >> 1);
        const float4 bb = *(const float4*)(bias + 4 * u);
#pragma unroll
        for (int mi = 0; mi < 2; mi++) {
            const float d0 = acc[mi][ni][0], d1 = acc[mi][ni][1];
            const float d2 = acc[mi][ni][2], d3 = acc[mi][ni][3];
            const float s0 = __shfl_xor_sync(0xffffffffu, odd ? d0 : d2, 1);
            const float s1 = __shfl_xor_sync(0xffffffffu, odd ? d1 : d3, 1);
            const float zi = (odd ? s0 : d0) + bb.x;
            const float zf = (odd ? s1 : d1) + bb.y;
            const float zg = (odd ? d2 : s0) + bb.z;
            const float zo = (odd ? d3 : s1) + bb.w;
            const int row = m0 + wm * 32 + mi * 16 + g + (odd ? 8 : 0);
            const float ig = fsigm(zi);
            const float fg = fsigm(zf);
            const float gg = ftanh(zg);
            const float og = fsigm(zo);
            const size_t off = (size_t)u * BATCH + row;   // col-major
            const float cn = fg * cbuf[off] + ig * gg;
            cbuf[off] = cn;
            hdst[off] = __float2half_rn(og * ftanh(cn));
        }
    }
}

__global__ __launch_bounds__(256, 2) void lstm1_first_kernel() {
    extern __shared__ char smem[];
    lstm_body<FEAT, H1, 80>(0, (blockIdx.x & 255) * 128, (blockIdx.x >> 8) * 128, smem);
}

// combined: lstm2(t) on blocks [0,256); lstm1(t+1) on blocks [256,1280)
__global__ __launch_bounds__(256, 2) void step_kernel(int t, int do_l1) {
    extern __shared__ char smem[];
    if (blockIdx.x < 256) {
        lstm_body<H1, H2, 80>(t, blockIdx.x * 128, 0, smem);
    } else if (do_l1) {
        const int bx = blockIdx.x - 256;
        lstm_body<FEAT, H1, 80>(t + 1, (bx & 255) * 128, (bx >> 8) * 128, smem);
    }
}

// ---------------- init & prepack ----------------
__global__ void init_state_kernel() {
    int idx = blockIdx.x * blockDim.x + threadIdx.x;
    int stride = gridDim.x * blockDim.x;
    const __half z = __float2half(0.f);
    for (int i = idx; i < BATCH * H1; i += stride) { g_h1[0][i] = z; g_c1[i] = 0.f; }
    for (int i = idx; i < BATCH * H2; i += stride) { g_h2[0][i] = z; g_c2[i] = 0.f; }
}

__global__ void prepack_kernel(const float* __restrict__ Wx1, const float* __restrict__ Wh1,
                               const float* __restrict__ b1,
                               const float* __restrict__ Wx2, const float* __restrict__ Wh2,
                               const float* __restrict__ b2,
                               const float* __restrict__ W_d1, const float* __restrict__ b_d1,
                               const float* __restrict__ gamma, const float* __restrict__ beta,
                               const float* __restrict__ mean, const float* __restrict__ var) {
    int idx = blockIdx.x * blockDim.x + threadIdx.x;
    int stride = gridDim.x * blockDim.x;
    {
        constexpr int K = FEAT + H1;
        for (int i = idx; i < 4 * H1 * K; i += stride) {
            int n = i / K, k = i % K;
            int u = n >> 2, g = n & 3, src = g * H1 + u;
            float w = (k < FEAT) ? Wx1[k * 4 * H1 + src] : Wh1[(k - FEAT) * 4 * H1 + src];
            g_Wp1[(size_t)n * K + k] = __float2half_rn(w);
        }
        for (int i = idx; i < 4 * H1; i += stride) {
            int u = i >> 2, g = i & 3;
            g_bc1[i] = b1[g * H1 + u];
        }
    }
    {
        constexpr int K = H1 + H2;
        for (int i = idx; i < 4 * H2 * K; i += stride) {
            int n = i / K, k = i % K;
            int u = n >> 2, g = n & 3, src = g * H2 + u;
            float w = (k < H1) ? Wx2[k * 4 * H2 + src] : Wh2[(k - H1) * 4 * H2 + src];
            g_Wp2[(size_t)n * K + k] = __float2half_rn(w);
        }
        for (int i = idx; i < 4 * H2; i += stride) {
            int u = i >> 2, g = i & 3;
            g_bc2[i] = b2[g * H2 + u];
        }
    }
    // Dense1 weights: bf16 hi/lo panel-major (verified)
    for (int i = idx; i < D_DENSE * D_IN; i += stride) {
        int n = i / D_IN, k = i % D_IN;
        int p = k >> 7, kk = k & 127;
        float w = W_d1[(size_t)k * D_DENSE + n];
        __nv_bfloat16 hi = __float2bfloat16(w);
        g_WpD[(size_t)n * 1024 + p * 256 + kk] = hi;
        g_WpD[(size_t)n * 1024 + p * 256 + 128 + kk] = __float2bfloat16(w - __bfloat162float(hi));
    }
    for (int i = idx; i < D_DENSE; i += stride) {
        float sc = gamma[i] * rsqrtf(var[i] + 1e-3f);
        g_d1sc[i] = sc;
        g_d1sh[i] = beta[i] + (b_d1[i] - mean[i]) * sc;
    }
}

// ---------------- Dense1 (verified bf16 3-term engine), act col-major single fp16 ---------
template <int K, int S>
__device__ __forceinline__ void warp_gemm3(uint32_t Asm, uint32_t Bsm,
                                           int wm, int wn, int lane, float acc[2][8][4]) {
    const uint32_t abase = Asm + ((((uint32_t)(wm * 32 + (lane & 15))) * S + ((lane >> 4) << 3)) << 1);
    const uint32_t bbase = Bsm + ((((uint32_t)(wn * 64 + ((lane >> 4) << 3) + (lane & 7))) * S
                                   + (((lane >> 3) & 1) << 3)) << 1);
#pragma unroll
    for (int term = 0; term < 3; term++) {
        const int ao = (term == 1) ? K : 0;
        const int bo = (term == 2) ? K : 0;
#pragma unroll
        for (int c = 0; c < K / 16; c++) {
            uint32_t a0[4], a1[4], b[4][4];
            ldsm4(a0, abase + ((ao + c * 16) << 1));
            ldsm4(a1, abase + ((16 * S + ao + c * 16) << 1));
#pragma unroll
            for (int nj = 0; nj < 4; nj++)
                ldsm4(b[nj], bbase + (((nj * 16) * S + bo + c * 16) << 1));
#pragma unroll
            for (int mi = 0; mi < 2; mi++) {
                const uint32_t* A = mi ? a1 : a0;
#pragma unroll
                for (int nj = 0; nj < 4; nj++) {
                    mma16816bf(acc[mi][2 * nj], A, b[nj][0], b[nj][1]);
                    mma16816bf(acc[mi][2 * nj + 1], A, b[nj][2], b[nj][3]);
                }
            }
        }
    }
}

__global__ __launch_bounds__(256, 1) void dense1_kernel(const float* __restrict__ x) {
    constexpr int KP = 128;
    constexpr int S = 2 * KP + 8;    // 264
    extern __shared__ char smem[];
    const uint32_t Asm = smem_u32(smem);
    const uint32_t Bsm = Asm + 128 * S * 2;
    char* const Bc = smem + 128 * S * 2;
    const int tid = threadIdx.x;
    const int lane = tid & 31, wid = tid >> 5;
    const int wm = wid & 3, wn = wid >> 2;
    const int m0 = blockIdx.x * 128, n0 = blockIdx.y * 128;

    float acc[2][8][4] = {};
    for (int p = 0; p < 4; p++) {
        for (int task = tid; task < 128 * 16; task += 256) {
            const int r = task >> 4, o = task & 15;
            const float* src = x + (size_t)(m0 + r) * D_IN + p * KP + o * 8;
            const float4 v0 = *(const float4*)src;
            const float4 v1 = *(const float4*)(src + 4);
            __nv_bfloat16 h[8], l[8];
            const float vv[8] = {v0.x, v0.y, v0.z, v0.w, v1.x, v1.y, v1.z, v1.w};
#pragma unroll
            for (int i = 0; i < 8; i++) {
                h[i] = __float2bfloat16(vv[i]);
                l[i] = __float2bfloat16(vv[i] - __bfloat162float(h[i]));
            }
            *(uint4*)(smem + ((size_t)r * S + o * 8) * 2) = *(uint4*)h;
            *(uint4*)(smem + ((size_t)r * S + KP + o * 8) * 2) = *(uint4*)l;
        }
        for (int task = tid; task < 128 * 32; task += 256) {
            const int n = task >> 5, o = task & 31;
            const uint4 v = *(const uint4*)(g_WpD + (size_t)(n0 + n) * 1024 + p * 256 + o * 8);
            *(uint4*)(Bc + ((size_t)n * S + o * 8) * 2) = v;
        }
        __syncthreads();
        warp_gemm3<KP, S>(Asm, Bsm, wm, wn, lane, acc);
        __syncthreads();
    }

    const int g = lane >> 2;
#pragma unroll
    for (int ni = 0; ni < 8; ni++) {
        const int n = n0 + wn * 64 + ni * 8 + (lane & 3) * 2;
        const float sc0 = g_d1sc[n], sc1 = g_d1sc[n + 1];
        const float sh0 = g_d1sh[n], sh1 = g_d1sh[n + 1];
#pragma unroll
        for (int mi = 0; mi < 2; mi++) {
#pragma unroll
            for (int half = 0; half < 2; half++) {
                const int row = m0 + wm * 32 + mi * 16 + g + half * 8;
                float v0 = acc[mi][ni][half * 2 + 0] * sc0 + sh0;
                float v1 = acc[mi][ni][half * 2 + 1] * sc1 + sh1;
                v0 = (v0 >= 0.f) ? v0 : 0.2f * v0;
                v1 = (v1 >= 0.f) ? v1 : 0.2f * v1;
                g_act[(size_t)n * BATCH + row] = __float2half_rn(v0);
                g_act[(size_t)(n + 1) * BATCH + row] = __float2half_rn(v1);
            }
        }
    }
}

// ---------------- Dense2 + softmax (col-major fp16 h2) ----------------
__global__ __launch_bounds__(256) void dense2_softmax_kernel(
    const float* __restrict__ Wd2, const float* __restrict__ bd2, float* __restrict__ out) {
    __shared__ float Ws[H2 * NCLS];
    __shared__ float bs[NCLS];
    int tid = threadIdx.x;
    for (int i = tid; i < H2 * NCLS; i += blockDim.x) Ws[i] = Wd2[i];
    if (tid < NCLS) bs[tid] = bd2[tid];
    __syncthreads();
    int row = blockIdx.x * blockDim.x + tid;
    const __half* hh = g_h2[0];  // t=15 writes buffer 0
    float acc[NCLS];
#pragma unroll
    for (int j = 0; j < NCLS; j++) acc[j] = bs[j];
#pragma unroll
    for (int k = 0; k < H2; k++) {
        float xv = __half2float(hh[(size_t)k * BATCH + row]);
#pragma unroll
        for (int j = 0; j < NCLS; j++) acc[j] += xv * Ws[k * NCLS + j];
    }
    float m = acc[0];
#pragma unroll
    for (int j = 1; j < NCLS; j++) m = fmaxf(m, acc[j]);
    float ssum = 0.f;
#pragma unroll
    for (int j = 0; j < NCLS; j++) { acc[j] = expf(acc[j] - m); ssum += acc[j]; }
    float inv = 1.f / ssum;
#pragma unroll
    for (int j = 0; j < NCLS; j++) out[(size_t)row * NCLS + j] = acc[j] * inv;
}

// ---------------- launch ----------------
extern "C" void kernel_launch(void* const* d_in, const int* in_sizes, int n_in,
                              void* d_out, int out_size) {
    const float* x        = (const float*)d_in[0];
    const float* W_d1     = (const float*)d_in[1];
    const float* b_d1     = (const float*)d_in[2];
    const float* bn_gamma = (const float*)d_in[3];
    const float* bn_beta  = (const float*)d_in[4];
    const float* bn_mean  = (const float*)d_in[5];
    const float* bn_var   = (const float*)d_in[6];
    const float* Wx1      = (const float*)d_in[7];
    const float* Wh1      = (const float*)d_in[8];
    const float* b1       = (const float*)d_in[9];
    const float* Wx2      = (const float*)d_in[10];
    const float* Wh2      = (const float*)d_in[11];
    const float* b2       = (const float*)d_in[12];
    const float* W_d2     = (const float*)d_in[13];
    const float* b_d2     = (const float*)d_in[14];
    float* out = (float*)d_out;

    const int SMD = 2 * 128 * (2 * 128 + 8) * 2;     // 135168

    cudaFuncSetAttribute(dense1_kernel, cudaFuncAttributeMaxDynamicSharedMemorySize, SMD);
    cudaFuncSetAttribute(lstm1_first_kernel, cudaFuncAttributeMaxDynamicSharedMemorySize, SM_STEP);
    cudaFuncSetAttribute(step_kernel, cudaFuncAttributeMaxDynamicSharedMemorySize, SM_STEP);

    prepack_kernel<<<256, 256>>>(Wx1, Wh1, b1, Wx2, Wh2, b2, W_d1, b_d1,
                                 bn_gamma, bn_beta, bn_mean, bn_var);
    init_state_kernel<<<2048, 256>>>();
    dense1_kernel<<<dim3(BATCH / 128, D_DENSE / 128), 256, SMD>>>(x);
    lstm1_first_kernel<<<1024, 256, SM_STEP>>>();
    for (int t = 0; t < TSTEPS; t++) {
        step_kernel<<<1280, 256, SM_STEP>>>(t, (t < TSTEPS - 1) ? 1 : 0);
    }
    dense2_softmax_kernel<<<BATCH / 256, 256>>>(W_d2, b_d2, out);
}

// round 14
// speedup vs baseline: 1.6587x; 1.1768x over previous
#include <cuda_runtime.h>
#include <cuda_bf16.h>
#include <cuda_fp16.h>
#include <math.h>
#include <stdint.h>

#define BATCH   32768
#define D_IN    512
#define D_DENSE 256
#define TSTEPS  16
#define FEAT    16
#define H1      128
#define H2      32
#define NCLS    10

// ---------------- state: COLUMN-major [feature][BATCH], single fp16 ----------------
__device__ __half g_act[D_DENSE * BATCH];
__device__ __half g_h1[2][H1 * BATCH];
__device__ __half g_h2[2][H2 * BATCH];
__device__ float g_c1[H1 * BATCH], g_c2[H2 * BATCH];

// prepacked LSTM weights: single fp16, row n (gate-interleaved), K cols
__device__ __half g_Wp1[(4 * H1) * (FEAT + H1)];   // [512][144]
__device__ __half g_Wp2[(4 * H2) * (H1 + H2)];     // [128][160]
// dense1 weights: bf16 hi/lo 3-term (verified engine)
__device__ __nv_bfloat16 g_WpD[D_DENSE * 2 * D_IN];
__device__ float g_bc1[4 * H1], g_bc2[4 * H2];
__device__ float g_d1sc[D_DENSE], g_d1sh[D_DENSE];

// ---------------- helpers ----------------
__device__ __forceinline__ uint32_t smem_u32(const void* p) {
    uint32_t a;
    asm("{ .reg .u64 t; cvta.to.shared.u64 t, %1; cvt.u32.u64 %0, t; }" : "=r"(a) : "l"(p));
    return a;
}
__device__ __forceinline__ float ftanh(float x) {
    float y;
    asm("tanh.approx.f32 %0, %1;" : "=f"(y) : "f"(x));
    return y;
}
__device__ __forceinline__ float fsigm(float x) { return 0.5f * ftanh(0.5f * x) + 0.5f; }

__device__ __forceinline__ void ldsm4(uint32_t* r, uint32_t addr) {
    asm volatile("ldmatrix.sync.aligned.m8n8.x4.shared.b16 {%0,%1,%2,%3}, [%4];"
                 : "=r"(r[0]), "=r"(r[1]), "=r"(r[2]), "=r"(r[3]) : "r"(addr));
}
__device__ __forceinline__ void ldsm4t(uint32_t* r, uint32_t addr) {
    asm volatile("ldmatrix.sync.aligned.m8n8.x4.trans.shared.b16 {%0,%1,%2,%3}, [%4];"
                 : "=r"(r[0]), "=r"(r[1]), "=r"(r[2]), "=r"(r[3]) : "r"(addr));
}
__device__ __forceinline__ void mma16816bf(float* d, const uint32_t* a, uint32_t b0, uint32_t b1) {
    asm volatile(
        "mma.sync.aligned.m16n8k16.row.col.f32.bf16.bf16.f32 "
        "{%0,%1,%2,%3}, {%4,%5,%6,%7}, {%8,%9}, {%0,%1,%2,%3};"
        : "+f"(d[0]), "+f"(d[1]), "+f"(d[2]), "+f"(d[3])
        : "r"(a[0]), "r"(a[1]), "r"(a[2]), "r"(a[3]), "r"(b0), "r"(b1));
}
__device__ __forceinline__ void mma16816h(float* d, const uint32_t* a, uint32_t b0, uint32_t b1) {
    asm volatile(
        "mma.sync.aligned.m16n8k16.row.col.f32.f16.f16.f32 "
        "{%0,%1,%2,%3}, {%4,%5,%6,%7}, {%8,%9}, {%0,%1,%2,%3};"
        : "+f"(d[0]), "+f"(d[1]), "+f"(d[2]), "+f"(d[3])
        : "r"(a[0]), "r"(a[1]), "r"(a[2]), "r"(a[3]), "r"(b0), "r"(b1));
}
__device__ __forceinline__ void cp16(uint32_t dst, const void* src) {
    asm volatile("cp.async.cg.shared.global [%0], [%1], 16;" :: "r"(dst), "l"(src));
}
#define CP_COMMIT() asm volatile("cp.async.commit_group;" ::: "memory")
#define CP_WAIT(n)  asm volatile("cp.async.wait_group %0;" :: "n"(n) : "memory")

// ===== fused LSTM step: single fp16, 2-chunk K-split pipeline, 512 thr 4Mx4N =====
// 512 threads, 16 warps, warp tile 32x32, CTA tile 128x128.
#define SROW 136
#define SBC  88
#define ASTG (80 * SROW * 2)         // stage A capacity (max chunk = 80 rows)
#define BSTG (128 * SBC * 2)
#define STG  (ASTG + BSTG)           // 44288
#define SM_STEP (2 * STG)            // 88576

template <int KX, int HID, int BK0>
__device__ __forceinline__ void lstm_body(int t, int m0, int n0, char* smemc) {
    constexpr int K = KX + HID;
    constexpr int BK1 = K - BK0;
    const int tid = threadIdx.x;
    const int lane = tid & 31, wid = tid >> 5;
    const int wm = wid & 3, wn = wid >> 2;    // 4 x 4
    const uint32_t sbase = smem_u32(smemc);
    const int p = t & 1;

    const __half *xsrc, *hsrc;
    __half* hdst;
    float* cbuf;
    const __half* W;
    const float* bias;
    int xoff;
    if (HID == H1) {
        xsrc = g_act; xoff = t * FEAT;
        hsrc = g_h1[p]; hdst = g_h1[p ^ 1];
        cbuf = g_c1; W = g_Wp1; bias = g_bc1;
    } else {
        xsrc = g_h1[p ^ 1]; xoff = 0;
        hsrc = g_h2[p]; hdst = g_h2[p ^ 1];
        cbuf = g_c2; W = g_Wp2; bias = g_bc2;
    }

    // ---- chunk 0 load: A cols [0,BK0), B cols [0,BK0) ----
    {
        const uint32_t As = sbase, Bs = sbase + ASTG;
#pragma unroll
        for (int task = tid; task < BK0 * 16; task += 512) {
            const int k = task >> 4, mg = task & 15;
            const __half* src = (k < KX)
                ? xsrc + (size_t)(xoff + k) * BATCH + m0 + mg * 8
                : hsrc + (size_t)(k - KX) * BATCH + m0 + mg * 8;
            cp16(As + (uint32_t)(k * SROW + mg * 8) * 2, src);
        }
#pragma unroll
        for (int task = tid; task < 128 * (BK0 / 8); task += 512) {
            const int n = task / (BK0 / 8), gg = task % (BK0 / 8);
            cp16(Bs + (uint32_t)(n * SBC + gg * 8) * 2,
                 W + (size_t)(n0 + n) * K + gg * 8);
        }
    }
    CP_COMMIT();
    // ---- chunk 1 load: A cols [BK0,K), B cols [BK0,K) ----
    {
        const uint32_t As = sbase + STG, Bs = sbase + STG + ASTG;
#pragma unroll
        for (int task = tid; task < BK1 * 16; task += 512) {
            const int k = task >> 4, mg = task & 15;
            const int col = BK0 + k;
            const __half* src = (col < KX)
                ? xsrc + (size_t)(xoff + col) * BATCH + m0 + mg * 8
                : hsrc + (size_t)(col - KX) * BATCH + m0 + mg * 8;
            cp16(As + (uint32_t)(k * SROW + mg * 8) * 2, src);
        }
#pragma unroll
        for (int task = tid; task < 128 * (BK1 / 8); task += 512) {
            const int n = task / (BK1 / 8), gg = task % (BK1 / 8);
            cp16(Bs + (uint32_t)(n * SBC + gg * 8) * 2,
                 W + (size_t)(n0 + n) * K + BK0 + gg * 8);
        }
    }
    CP_COMMIT();

    const uint32_t arow = (uint32_t)((lane & 7) + ((lane >> 4) << 3));
    const uint32_t acol = (uint32_t)(wm * 32 + (((lane >> 3) & 1) << 3));
    const uint32_t brow = (uint32_t)(wn * 32 + ((lane >> 4) << 3) + (lane & 7));
    const uint32_t bcol8 = (uint32_t)(((lane >> 3) & 1) << 3);
    float acc[2][4][4] = {};

    // ---- compute chunk 0 (chunk 1 load in flight) ----
    CP_WAIT(1);
    __syncthreads();
#pragma unroll
    for (int kk = 0; kk < BK0 / 16; kk++) {
        uint32_t a0[4], a1[4];
        const uint32_t hr = (uint32_t)(kk * 16) + arow;
        ldsm4t(a0, sbase + (hr * SROW + acol) * 2);
        ldsm4t(a1, sbase + (hr * SROW + acol + 16) * 2);
        const uint32_t cofs = (uint32_t)(kk * 16) + bcol8;
#pragma unroll
        for (int nj = 0; nj < 2; nj++) {
            uint32_t b[4];
            ldsm4(b, sbase + ASTG + ((brow + nj * 16) * SBC + cofs) * 2);
            mma16816h(acc[0][2 * nj], a0, b[0], b[1]);
            mma16816h(acc[0][2 * nj + 1], a0, b[2], b[3]);
            mma16816h(acc[1][2 * nj], a1, b[0], b[1]);
            mma16816h(acc[1][2 * nj + 1], a1, b[2], b[3]);
        }
    }
    // ---- compute chunk 1 ----
    CP_WAIT(0);
    __syncthreads();
#pragma unroll
    for (int kk = 0; kk < BK1 / 16; kk++) {
        uint32_t a0[4], a1[4];
        const uint32_t hr = (uint32_t)(kk * 16) + arow;
        ldsm4t(a0, sbase + STG + (hr * SROW + acol) * 2);
        ldsm4t(a1, sbase + STG + (hr * SROW + acol + 16) * 2);
        const uint32_t cofs = (uint32_t)(kk * 16) + bcol8;
#pragma unroll
        for (int nj = 0; nj < 2; nj++) {
            uint32_t b[4];
            ldsm4(b, sbase + STG + ASTG + ((brow + nj * 16) * SBC + cofs) * 2);
            mma16816h(acc[0][2 * nj], a0, b[0], b[1]);
            mma16816h(acc[0][2 * nj + 1], a0, b[2], b[3]);
            mma16816h(acc[1][2 * nj], a1, b[0], b[1]);
            mma16816h(acc[1][2 * nj + 1], a1, b[2], b[3]);
        }
    }

    // epilogue: pair-swap gates; col-major fp16 state -> coalesced stores
    const int g = lane >> 2;
    const bool odd = lane & 1;
#pragma unroll
    for (int ni = 0; ni < 4; ni++) {
        const int u = ((n0 + wn * 32 + ni * 8) >> 2) + ((lane & 2) >> 1);
        const float4 bb = *(const float4*)(bias + 4 * u);
#pragma unroll
        for (int mi = 0; mi < 2; mi++) {
            const float d0 = acc[mi][ni][0], d1 = acc[mi][ni][1];
            const float d2 = acc[mi][ni][2], d3 = acc[mi][ni][3];
            const float s0 = __shfl_xor_sync(0xffffffffu, odd ? d0 : d2, 1);
            const float s1 = __shfl_xor_sync(0xffffffffu, odd ? d1 : d3, 1);
            const float zi = (odd ? s0 : d0) + bb.x;
            const float zf = (odd ? s1 : d1) + bb.y;
            const float zg = (odd ? d2 : s0) + bb.z;
            const float zo = (odd ? d3 : s1) + bb.w;
            const int row = m0 + wm * 32 + mi * 16 + g + (odd ? 8 : 0);
            const float ig = fsigm(zi);
            const float fg = fsigm(zf);
            const float gg = ftanh(zg);
            const float og = fsigm(zo);
            const size_t off = (size_t)u * BATCH + row;   // col-major
            const float cn = fg * cbuf[off] + ig * gg;
            cbuf[off] = cn;
            hdst[off] = __float2half_rn(og * ftanh(cn));
        }
    }
}

__global__ __launch_bounds__(512, 2) void lstm1_first_kernel() {
    extern __shared__ char smem[];
    lstm_body<FEAT, H1, 80>(0, (blockIdx.x & 255) * 128, (blockIdx.x >> 8) * 128, smem);
}

// combined: lstm2(t) on blocks [0,256); lstm1(t+1) on blocks [256,1280)
__global__ __launch_bounds__(512, 2) void step_kernel(int t, int do_l1) {
    extern __shared__ char smem[];
    if (blockIdx.x < 256) {
        lstm_body<H1, H2, 80>(t, blockIdx.x * 128, 0, smem);
    } else if (do_l1) {
        const int bx = blockIdx.x - 256;
        lstm_body<FEAT, H1, 80>(t + 1, (bx & 255) * 128, (bx >> 8) * 128, smem);
    }
}

// ---------------- init & prepack ----------------
__global__ void init_state_kernel() {
    int idx = blockIdx.x * blockDim.x + threadIdx.x;
    int stride = gridDim.x * blockDim.x;
    const __half z = __float2half(0.f);
    for (int i = idx; i < BATCH * H1; i += stride) { g_h1[0][i] = z; g_c1[i] = 0.f; }
    for (int i = idx; i < BATCH * H2; i += stride) { g_h2[0][i] = z; g_c2[i] = 0.f; }
}

__global__ void prepack_kernel(const float* __restrict__ Wx1, const float* __restrict__ Wh1,
                               const float* __restrict__ b1,
                               const float* __restrict__ Wx2, const float* __restrict__ Wh2,
                               const float* __restrict__ b2,
                               const float* __restrict__ W_d1, const float* __restrict__ b_d1,
                               const float* __restrict__ gamma, const float* __restrict__ beta,
                               const float* __restrict__ mean, const float* __restrict__ var) {
    int idx = blockIdx.x * blockDim.x + threadIdx.x;
    int stride = gridDim.x * blockDim.x;
    {
        constexpr int K = FEAT + H1;
        for (int i = idx; i < 4 * H1 * K; i += stride) {
            int n = i / K, k = i % K;
            int u = n >> 2, g = n & 3, src = g * H1 + u;
            float w = (k < FEAT) ? Wx1[k * 4 * H1 + src] : Wh1[(k - FEAT) * 4 * H1 + src];
            g_Wp1[(size_t)n * K + k] = __float2half_rn(w);
        }
        for (int i = idx; i < 4 * H1; i += stride) {
            int u = i >> 2, g = i & 3;
            g_bc1[i] = b1[g * H1 + u];
        }
    }
    {
        constexpr int K = H1 + H2;
        for (int i = idx; i < 4 * H2 * K; i += stride) {
            int n = i / K, k = i % K;
            int u = n >> 2, g = n & 3, src = g * H2 + u;
            float w = (k < H1) ? Wx2[k * 4 * H2 + src] : Wh2[(k - H1) * 4 * H2 + src];
            g_Wp2[(size_t)n * K + k] = __float2half_rn(w);
        }
        for (int i = idx; i < 4 * H2; i += stride) {
            int u = i >> 2, g = i & 3;
            g_bc2[i] = b2[g * H2 + u];
        }
    }
    // Dense1 weights: bf16 hi/lo panel-major (verified)
    for (int i = idx; i < D_DENSE * D_IN; i += stride) {
        int n = i / D_IN, k = i % D_IN;
        int p = k >> 7, kk = k & 127;
        float w = W_d1[(size_t)k * D_DENSE + n];
        __nv_bfloat16 hi = __float2bfloat16(w);
        g_WpD[(size_t)n * 1024 + p * 256 + kk] = hi;
        g_WpD[(size_t)n * 1024 + p * 256 + 128 + kk] = __float2bfloat16(w - __bfloat162float(hi));
    }
    for (int i = idx; i < D_DENSE; i += stride) {
        float sc = gamma[i] * rsqrtf(var[i] + 1e-3f);
        g_d1sc[i] = sc;
        g_d1sh[i] = beta[i] + (b_d1[i] - mean[i]) * sc;
    }
}

// ---------------- Dense1 (verified bf16 3-term engine), act col-major single fp16 ---------
template <int K, int S>
__device__ __forceinline__ void warp_gemm3(uint32_t Asm, uint32_t Bsm,
                                           int wm, int wn, int lane, float acc[2][8][4]) {
    const uint32_t abase = Asm + ((((uint32_t)(wm * 32 + (lane & 15))) * S + ((lane >> 4) << 3)) << 1);
    const uint32_t bbase = Bsm + ((((uint32_t)(wn * 64 + ((lane >> 4) << 3) + (lane & 7))) * S
                                   + (((lane >> 3) & 1) << 3)) << 1);
#pragma unroll
    for (int term = 0; term < 3; term++) {
        const int ao = (term == 1) ? K : 0;
        const int bo = (term == 2) ? K : 0;
#pragma unroll
        for (int c = 0; c < K / 16; c++) {
            uint32_t a0[4], a1[4], b[4][4];
            ldsm4(a0, abase + ((ao + c * 16) << 1));
            ldsm4(a1, abase + ((16 * S + ao + c * 16) << 1));
#pragma unroll
            for (int nj = 0; nj < 4; nj++)
                ldsm4(b[nj], bbase + (((nj * 16) * S + bo + c * 16) << 1));
#pragma unroll
            for (int mi = 0; mi < 2; mi++) {
                const uint32_t* A = mi ? a1 : a0;
#pragma unroll
                for (int nj = 0; nj < 4; nj++) {
                    mma16816bf(acc[mi][2 * nj], A, b[nj][0], b[nj][1]);
                    mma16816bf(acc[mi][2 * nj + 1], A, b[nj][2], b[nj][3]);
                }
            }
        }
    }
}

__global__ __launch_bounds__(256, 1) void dense1_kernel(const float* __restrict__ x) {
    constexpr int KP = 128;
    constexpr int S = 2 * KP + 8;    // 264
    extern __shared__ char smem[];
    const uint32_t Asm = smem_u32(smem);
    const uint32_t Bsm = Asm + 128 * S * 2;
    char* const Bc = smem + 128 * S * 2;
    const int tid = threadIdx.x;
    const int lane = tid & 31, wid = tid >> 5;
    const int wm = wid & 3, wn = wid >> 2;
    const int m0 = blockIdx.x * 128, n0 = blockIdx.y * 128;

    float acc[2][8][4] = {};
    for (int p = 0; p < 4; p++) {
        for (int task = tid; task < 128 * 16; task += 256) {
            const int r = task >> 4, o = task & 15;
            const float* src = x + (size_t)(m0 + r) * D_IN + p * KP + o * 8;
            const float4 v0 = *(const float4*)src;
            const float4 v1 = *(const float4*)(src + 4);
            __nv_bfloat16 h[8], l[8];
            const float vv[8] = {v0.x, v0.y, v0.z, v0.w, v1.x, v1.y, v1.z, v1.w};
#pragma unroll
            for (int i = 0; i < 8; i++) {
                h[i] = __float2bfloat16(vv[i]);
                l[i] = __float2bfloat16(vv[i] - __bfloat162float(h[i]));
            }
            *(uint4*)(smem + ((size_t)r * S + o * 8) * 2) = *(uint4*)h;
            *(uint4*)(smem + ((size_t)r * S + KP + o * 8) * 2) = *(uint4*)l;
        }
        for (int task = tid; task < 128 * 32; task += 256) {
            const int n = task >> 5, o = task & 31;
            const uint4 v = *(const uint4*)(g_WpD + (size_t)(n0 + n) * 1024 + p * 256 + o * 8);
            *(uint4*)(Bc + ((size_t)n * S + o * 8) * 2) = v;
        }
        __syncthreads();
        warp_gemm3<KP, S>(Asm, Bsm, wm, wn, lane, acc);
        __syncthreads();
    }

    const int g = lane >> 2;
#pragma unroll
    for (int ni = 0; ni < 8; ni++) {
        const int n = n0 + wn * 64 + ni * 8 + (lane & 3) * 2;
        const float sc0 = g_d1sc[n], sc1 = g_d1sc[n + 1];
        const float sh0 = g_d1sh[n], sh1 = g_d1sh[n + 1];
#pragma unroll
        for (int mi = 0; mi < 2; mi++) {
#pragma unroll
            for (int half = 0; half < 2; half++) {
                const int row = m0 + wm * 32 + mi * 16 + g + half * 8;
                float v0 = acc[mi][ni][half * 2 + 0] * sc0 + sh0;
                float v1 = acc[mi][ni][half * 2 + 1] * sc1 + sh1;
                v0 = (v0 >= 0.f) ? v0 : 0.2f * v0;
                v1 = (v1 >= 0.f) ? v1 : 0.2f * v1;
                g_act[(size_t)n * BATCH + row] = __float2half_rn(v0);
                g_act[(size_t)(n + 1) * BATCH + row] = __float2half_rn(v1);
            }
        }
    }
}

// ---------------- Dense2 + softmax (col-major fp16 h2) ----------------
__global__ __launch_bounds__(256) void dense2_softmax_kernel(
    const float* __restrict__ Wd2, const float* __restrict__ bd2, float* __restrict__ out) {
    __shared__ float Ws[H2 * NCLS];
    __shared__ float bs[NCLS];
    int tid = threadIdx.x;
    for (int i = tid; i < H2 * NCLS; i += blockDim.x) Ws[i] = Wd2[i];
    if (tid < NCLS) bs[tid] = bd2[tid];
    __syncthreads();
    int row = blockIdx.x * blockDim.x + tid;
    const __half* hh = g_h2[0];  // t=15 writes buffer 0
    float acc[NCLS];
#pragma unroll
    for (int j = 0; j < NCLS; j++) acc[j] = bs[j];
#pragma unroll
    for (int k = 0; k < H2; k++) {
        float xv = __half2float(hh[(size_t)k * BATCH + row]);
#pragma unroll
        for (int j = 0; j < NCLS; j++) acc[j] += xv * Ws[k * NCLS + j];
    }
    float m = acc[0];
#pragma unroll
    for (int j = 1; j < NCLS; j++) m = fmaxf(m, acc[j]);
    float ssum = 0.f;
#pragma unroll
    for (int j = 0; j < NCLS; j++) { acc[j] = expf(acc[j] - m); ssum += acc[j]; }
    float inv = 1.f / ssum;
#pragma unroll
    for (int j = 0; j < NCLS; j++) out[(size_t)row * NCLS + j] = acc[j] * inv;
}

// ---------------- launch ----------------
extern "C" void kernel_launch(void* const* d_in, const int* in_sizes, int n_in,
                              void* d_out, int out_size) {
    const float* x        = (const float*)d_in[0];
    const float* W_d1     = (const float*)d_in[1];
    const float* b_d1     = (const float*)d_in[2];
    const float* bn_gamma = (const float*)d_in[3];
    const float* bn_beta  = (const float*)d_in[4];
    const float* bn_mean  = (const float*)d_in[5];
    const float* bn_var   = (const float*)d_in[6];
    const float* Wx1      = (const float*)d_in[7];
    const float* Wh1      = (const float*)d_in[8];
    const float* b1       = (const float*)d_in[9];
    const float* Wx2      = (const float*)d_in[10];
    const float* Wh2      = (const float*)d_in[11];
    const float* b2       = (const float*)d_in[12];
    const float* W_d2     = (const float*)d_in[13];
    const float* b_d2     = (const float*)d_in[14];
    float* out = (float*)d_out;

    const int SMD = 2 * 128 * (2 * 128 + 8) * 2;     // 135168

    cudaFuncSetAttribute(dense1_kernel, cudaFuncAttributeMaxDynamicSharedMemorySize, SMD);
    cudaFuncSetAttribute(lstm1_first_kernel, cudaFuncAttributeMaxDynamicSharedMemorySize, SM_STEP);
    cudaFuncSetAttribute(step_kernel, cudaFuncAttributeMaxDynamicSharedMemorySize, SM_STEP);

    prepack_kernel<<<256, 256>>>(Wx1, Wh1, b1, Wx2, Wh2, b2, W_d1, b_d1,
                                 bn_gamma, bn_beta, bn_mean, bn_var);
    init_state_kernel<<<2048, 256>>>();
    dense1_kernel<<<dim3(BATCH / 128, D_DENSE / 128), 256, SMD>>>(x);
    lstm1_first_kernel<<<1024, 512, SM_STEP>>>();
    for (int t = 0; t < TSTEPS; t++) {
        step_kernel<<<1280, 512, SM_STEP>>>(t, (t < TSTEPS - 1) ? 1 : 0);
    }
    dense2_softmax_kernel<<<BATCH / 256, 256>>>(W_d2, b_d2, out);
}

// round 15
// speedup vs baseline: 1.8612x; 1.1221x over previous
#include <cuda_runtime.h>
#include <cuda_bf16.h>
#include <cuda_fp16.h>
#include <math.h>
#include <stdint.h>

#define BATCH   32768
#define D_IN    512
#define D_DENSE 256
#define TSTEPS  16
#define FEAT    16
#define H1      128
#define H2      32
#define NCLS    10

// ---------------- state: COLUMN-major [feature][BATCH], single fp16 ----------------
__device__ __half g_act[D_DENSE * BATCH];
__device__ __half g_h1[2][H1 * BATCH];
__device__ __half g_h2[2][H2 * BATCH];
__device__ float g_c1[H1 * BATCH], g_c2[H2 * BATCH];

// prepacked weights: single fp16
__device__ __half g_Wp1[(4 * H1) * (FEAT + H1)];   // [512][144] gate-interleaved
__device__ __half g_Wp2[(4 * H2) * (H1 + H2)];     // [128][160]
__device__ __half g_WpD[D_DENSE * D_IN];           // [256][512] row n, K cols
__device__ float g_bc1[4 * H1], g_bc2[4 * H2];
__device__ float g_d1sc[D_DENSE], g_d1sh[D_DENSE];

// ---------------- helpers ----------------
__device__ __forceinline__ uint32_t smem_u32(const void* p) {
    uint32_t a;
    asm("{ .reg .u64 t; cvta.to.shared.u64 t, %1; cvt.u32.u64 %0, t; }" : "=r"(a) : "l"(p));
    return a;
}
__device__ __forceinline__ float ftanh(float x) {
    float y;
    asm("tanh.approx.f32 %0, %1;" : "=f"(y) : "f"(x));
    return y;
}
__device__ __forceinline__ float fsigm(float x) { return 0.5f * ftanh(0.5f * x) + 0.5f; }

__device__ __forceinline__ void ldsm4(uint32_t* r, uint32_t addr) {
    asm volatile("ldmatrix.sync.aligned.m8n8.x4.shared.b16 {%0,%1,%2,%3}, [%4];"
                 : "=r"(r[0]), "=r"(r[1]), "=r"(r[2]), "=r"(r[3]) : "r"(addr));
}
__device__ __forceinline__ void ldsm4t(uint32_t* r, uint32_t addr) {
    asm volatile("ldmatrix.sync.aligned.m8n8.x4.trans.shared.b16 {%0,%1,%2,%3}, [%4];"
                 : "=r"(r[0]), "=r"(r[1]), "=r"(r[2]), "=r"(r[3]) : "r"(addr));
}
__device__ __forceinline__ void mma16816h(float* d, const uint32_t* a, uint32_t b0, uint32_t b1) {
    asm volatile(
        "mma.sync.aligned.m16n8k16.row.col.f32.f16.f16.f32 "
        "{%0,%1,%2,%3}, {%4,%5,%6,%7}, {%8,%9}, {%0,%1,%2,%3};"
        : "+f"(d[0]), "+f"(d[1]), "+f"(d[2]), "+f"(d[3])
        : "r"(a[0]), "r"(a[1]), "r"(a[2]), "r"(a[3]), "r"(b0), "r"(b1));
}
__device__ __forceinline__ void cp16(uint32_t dst, const void* src) {
    asm volatile("cp.async.cg.shared.global [%0], [%1], 16;" :: "r"(dst), "l"(src));
}
#define CP_COMMIT() asm volatile("cp.async.commit_group;" ::: "memory")
#define CP_WAIT(n)  asm volatile("cp.async.wait_group %0;" :: "n"(n) : "memory")

// ===== fused LSTM step (R14 verified): single fp16, 2-chunk K-split, 512 thr 4Mx4N =====
#define SROW 136
#define SBC  88
#define ASTG (80 * SROW * 2)
#define BSTG (128 * SBC * 2)
#define STG  (ASTG + BSTG)           // 44288
#define SM_STEP (2 * STG)            // 88576

template <int KX, int HID, int BK0>
__device__ __forceinline__ void lstm_body(int t, int m0, int n0, char* smemc) {
    constexpr int K = KX + HID;
    constexpr int BK1 = K - BK0;
    const int tid = threadIdx.x;
    const int lane = tid & 31, wid = tid >> 5;
    const int wm = wid & 3, wn = wid >> 2;    // 4 x 4
    const uint32_t sbase = smem_u32(smemc);
    const int p = t & 1;

    const __half *xsrc, *hsrc;
    __half* hdst;
    float* cbuf;
    const __half* W;
    const float* bias;
    int xoff;
    if (HID == H1) {
        xsrc = g_act; xoff = t * FEAT;
        hsrc = g_h1[p]; hdst = g_h1[p ^ 1];
        cbuf = g_c1; W = g_Wp1; bias = g_bc1;
    } else {
        xsrc = g_h1[p ^ 1]; xoff = 0;
        hsrc = g_h2[p]; hdst = g_h2[p ^ 1];
        cbuf = g_c2; W = g_Wp2; bias = g_bc2;
    }

    // ---- chunk 0 load ----
    {
        const uint32_t As = sbase, Bs = sbase + ASTG;
#pragma unroll
        for (int task = tid; task < BK0 * 16; task += 512) {
            const int k = task >> 4, mg = task & 15;
            const __half* src = (k < KX)
                ? xsrc + (size_t)(xoff + k) * BATCH + m0 + mg * 8
                : hsrc + (size_t)(k - KX) * BATCH + m0 + mg * 8;
            cp16(As + (uint32_t)(k * SROW + mg * 8) * 2, src);
        }
#pragma unroll
        for (int task = tid; task < 128 * (BK0 / 8); task += 512) {
            const int n = task / (BK0 / 8), gg = task % (BK0 / 8);
            cp16(Bs + (uint32_t)(n * SBC + gg * 8) * 2,
                 W + (size_t)(n0 + n) * K + gg * 8);
        }
    }
    CP_COMMIT();
    // ---- chunk 1 load ----
    {
        const uint32_t As = sbase + STG, Bs = sbase + STG + ASTG;
#pragma unroll
        for (int task = tid; task < BK1 * 16; task += 512) {
            const int k = task >> 4, mg = task & 15;
            const int col = BK0 + k;
            const __half* src = (col < KX)
                ? xsrc + (size_t)(xoff + col) * BATCH + m0 + mg * 8
                : hsrc + (size_t)(col - KX) * BATCH + m0 + mg * 8;
            cp16(As + (uint32_t)(k * SROW + mg * 8) * 2, src);
        }
#pragma unroll
        for (int task = tid; task < 128 * (BK1 / 8); task += 512) {
            const int n = task / (BK1 / 8), gg = task % (BK1 / 8);
            cp16(Bs + (uint32_t)(n * SBC + gg * 8) * 2,
                 W + (size_t)(n0 + n) * K + BK0 + gg * 8);
        }
    }
    CP_COMMIT();

    const uint32_t arow = (uint32_t)((lane & 7) + ((lane >> 4) << 3));
    const uint32_t acol = (uint32_t)(wm * 32 + (((lane >> 3) & 1) << 3));
    const uint32_t brow = (uint32_t)(wn * 32 + ((lane >> 4) << 3) + (lane & 7));
    const uint32_t bcol8 = (uint32_t)(((lane >> 3) & 1) << 3);
    float acc[2][4][4] = {};

    CP_WAIT(1);
    __syncthreads();
#pragma unroll
    for (int kk = 0; kk < BK0 / 16; kk++) {
        uint32_t a0[4], a1[4];
        const uint32_t hr = (uint32_t)(kk * 16) + arow;
        ldsm4t(a0, sbase + (hr * SROW + acol) * 2);
        ldsm4t(a1, sbase + (hr * SROW + acol + 16) * 2);
        const uint32_t cofs = (uint32_t)(kk * 16) + bcol8;
#pragma unroll
        for (int nj = 0; nj < 2; nj++) {
            uint32_t b[4];
            ldsm4(b, sbase + ASTG + ((brow + nj * 16) * SBC + cofs) * 2);
            mma16816h(acc[0][2 * nj], a0, b[0], b[1]);
            mma16816h(acc[0][2 * nj + 1], a0, b[2], b[3]);
            mma16816h(acc[1][2 * nj], a1, b[0], b[1]);
            mma16816h(acc[1][2 * nj + 1], a1, b[2], b[3]);
        }
    }
    CP_WAIT(0);
    __syncthreads();
#pragma unroll
    for (int kk = 0; kk < BK1 / 16; kk++) {
        uint32_t a0[4], a1[4];
        const uint32_t hr = (uint32_t)(kk * 16) + arow;
        ldsm4t(a0, sbase + STG + (hr * SROW + acol) * 2);
        ldsm4t(a1, sbase + STG + (hr * SROW + acol + 16) * 2);
        const uint32_t cofs = (uint32_t)(kk * 16) + bcol8;
#pragma unroll
        for (int nj = 0; nj < 2; nj++) {
            uint32_t b[4];
            ldsm4(b, sbase + STG + ASTG + ((brow + nj * 16) * SBC + cofs) * 2);
            mma16816h(acc[0][2 * nj], a0, b[0], b[1]);
            mma16816h(acc[0][2 * nj + 1], a0, b[2], b[3]);
            mma16816h(acc[1][2 * nj], a1, b[0], b[1]);
            mma16816h(acc[1][2 * nj + 1], a1, b[2], b[3]);
        }
    }

    // epilogue
    const int g = lane >> 2;
    const bool odd = lane & 1;
#pragma unroll
    for (int ni = 0; ni < 4; ni++) {
        const int u = ((n0 + wn * 32 + ni * 8) >> 2) + ((lane & 2) >> 1);
        const float4 bb = *(const float4*)(bias + 4 * u);
#pragma unroll
        for (int mi = 0; mi < 2; mi++) {
            const float d0 = acc[mi][ni][0], d1 = acc[mi][ni][1];
            const float d2 = acc[mi][ni][2], d3 = acc[mi][ni][3];
            const float s0 = __shfl_xor_sync(0xffffffffu, odd ? d0 : d2, 1);
            const float s1 = __shfl_xor_sync(0xffffffffu, odd ? d1 : d3, 1);
            const float zi = (odd ? s0 : d0) + bb.x;
            const float zf = (odd ? s1 : d1) + bb.y;
            const float zg = (odd ? d2 : s0) + bb.z;
            const float zo = (odd ? d3 : s1) + bb.w;
            const int row = m0 + wm * 32 + mi * 16 + g + (odd ? 8 : 0);
            const float ig = fsigm(zi);
            const float fg = fsigm(zf);
            const float gg = ftanh(zg);
            const float og = fsigm(zo);
            const size_t off = (size_t)u * BATCH + row;
            const float cn = fg * cbuf[off] + ig * gg;
            cbuf[off] = cn;
            hdst[off] = __float2half_rn(og * ftanh(cn));
        }
    }
}

__global__ __launch_bounds__(512, 2) void lstm1_first_kernel() {
    extern __shared__ char smem[];
    lstm_body<FEAT, H1, 80>(0, (blockIdx.x & 255) * 128, (blockIdx.x >> 8) * 128, smem);
}

__global__ __launch_bounds__(512, 2) void step_kernel(int t, int do_l1) {
    extern __shared__ char smem[];
    if (blockIdx.x < 256) {
        lstm_body<H1, H2, 80>(t, blockIdx.x * 128, 0, smem);
    } else if (do_l1) {
        const int bx = blockIdx.x - 256;
        lstm_body<FEAT, H1, 80>(t + 1, (bx & 255) * 128, (bx >> 8) * 128, smem);
    }
}

// ---------------- init & prepack ----------------
__global__ void init_state_kernel() {
    int idx = blockIdx.x * blockDim.x + threadIdx.x;
    int stride = gridDim.x * blockDim.x;
    const __half z = __float2half(0.f);
    for (int i = idx; i < BATCH * H1; i += stride) { g_h1[0][i] = z; g_c1[i] = 0.f; }
    for (int i = idx; i < BATCH * H2; i += stride) { g_h2[0][i] = z; g_c2[i] = 0.f; }
}

__global__ void prepack_kernel(const float* __restrict__ Wx1, const float* __restrict__ Wh1,
                               const float* __restrict__ b1,
                               const float* __restrict__ Wx2, const float* __restrict__ Wh2,
                               const float* __restrict__ b2,
                               const float* __restrict__ W_d1, const float* __restrict__ b_d1,
                               const float* __restrict__ gamma, const float* __restrict__ beta,
                               const float* __restrict__ mean, const float* __restrict__ var) {
    int idx = blockIdx.x * blockDim.x + threadIdx.x;
    int stride = gridDim.x * blockDim.x;
    {
        constexpr int K = FEAT + H1;
        for (int i = idx; i < 4 * H1 * K; i += stride) {
            int n = i / K, k = i % K;
            int u = n >> 2, g = n & 3, src = g * H1 + u;
            float w = (k < FEAT) ? Wx1[k * 4 * H1 + src] : Wh1[(k - FEAT) * 4 * H1 + src];
            g_Wp1[(size_t)n * K + k] = __float2half_rn(w);
        }
        for (int i = idx; i < 4 * H1; i += stride) {
            int u = i >> 2, g = i & 3;
            g_bc1[i] = b1[g * H1 + u];
        }
    }
    {
        constexpr int K = H1 + H2;
        for (int i = idx; i < 4 * H2 * K; i += stride) {
            int n = i / K, k = i % K;
            int u = n >> 2, g = n & 3, src = g * H2 + u;
            float w = (k < H1) ? Wx2[k * 4 * H2 + src] : Wh2[(k - H1) * 4 * H2 + src];
            g_Wp2[(size_t)n * K + k] = __float2half_rn(w);
        }
        for (int i = idx; i < 4 * H2; i += stride) {
            int u = i >> 2, g = i & 3;
            g_bc2[i] = b2[g * H2 + u];
        }
    }
    // Dense1 weights: single fp16, row n (out feature), K=512 cols
    for (int i = idx; i < D_DENSE * D_IN; i += stride) {
        int n = i / D_IN, k = i % D_IN;
        g_WpD[(size_t)n * D_IN + k] = __float2half_rn(W_d1[(size_t)k * D_DENSE + n]);
    }
    for (int i = idx; i < D_DENSE; i += stride) {
        float sc = gamma[i] * rsqrtf(var[i] + 1e-3f);
        g_d1sc[i] = sc;
        g_d1sh[i] = beta[i] + (b_d1[i] - mean[i]) * sc;
    }
}

// ---------------- Dense1: single fp16 1-term, 512 thr 4Mx4N, BN+leaky fused ----------------
// A: x fp32 -> fp16 row-major [128 rows][136], B: WpD panel [128 n][136]
#define D1S 136
#define D1_ASZ (128 * D1S * 2)
#define SMD (2 * D1_ASZ)   // 69632

__global__ __launch_bounds__(512, 2) void dense1_kernel(const float* __restrict__ x) {
    constexpr int KP = 128;   // K per panel, 4 panels
    extern __shared__ char smem[];
    const uint32_t Asm = smem_u32(smem);
    const uint32_t Bsm = Asm + D1_ASZ;
    const int tid = threadIdx.x;
    const int lane = tid & 31, wid = tid >> 5;
    const int wm = wid & 3, wn = wid >> 2;   // 4 x 4
    const int m0 = blockIdx.x * 128, n0 = blockIdx.y * 128;

    const uint32_t abase = Asm + ((((uint32_t)(wm * 32 + (lane & 15))) * D1S + ((lane >> 4) << 3)) << 1);
    const uint32_t brow = (uint32_t)(wn * 32 + ((lane >> 4) << 3) + (lane & 7));
    const uint32_t bcol8 = (uint32_t)(((lane >> 3) & 1) << 3);

    float acc[2][4][4] = {};
    for (int p = 0; p < 4; p++) {
        // A: convert fp32 -> fp16
        for (int task = tid; task < 128 * 16; task += 512) {
            const int r = task >> 4, o = task & 15;
            const float* src = x + (size_t)(m0 + r) * D_IN + p * KP + o * 8;
            const float4 v0 = *(const float4*)src;
            const float4 v1 = *(const float4*)(src + 4);
            __half h[8];
            h[0] = __float2half_rn(v0.x); h[1] = __float2half_rn(v0.y);
            h[2] = __float2half_rn(v0.z); h[3] = __float2half_rn(v0.w);
            h[4] = __float2half_rn(v1.x); h[5] = __float2half_rn(v1.y);
            h[6] = __float2half_rn(v1.z); h[7] = __float2half_rn(v1.w);
            *(uint4*)(smem + ((size_t)r * D1S + o * 8) * 2) = *(uint4*)h;
        }
        // B: cp.async copy
        for (int task = tid; task < 128 * 16; task += 512) {
            const int n = task >> 4, gg = task & 15;
            cp16(Bsm + (uint32_t)(n * D1S + gg * 8) * 2,
                 g_WpD + (size_t)(n0 + n) * D_IN + p * KP + gg * 8);
        }
        CP_COMMIT();
        CP_WAIT(0);
        __syncthreads();
#pragma unroll
        for (int kk = 0; kk < KP / 16; kk++) {
            uint32_t a0[4], a1[4];
            ldsm4(a0, abase + (kk * 16) * 2);
            ldsm4(a1, abase + (16 * D1S + kk * 16) * 2);
            const uint32_t cofs = (uint32_t)(kk * 16) + bcol8;
#pragma unroll
            for (int nj = 0; nj < 2; nj++) {
                uint32_t b[4];
                ldsm4(b, Bsm + ((brow + nj * 16) * D1S + cofs) * 2);
                mma16816h(acc[0][2 * nj], a0, b[0], b[1]);
                mma16816h(acc[0][2 * nj + 1], a0, b[2], b[3]);
                mma16816h(acc[1][2 * nj], a1, b[0], b[1]);
                mma16816h(acc[1][2 * nj + 1], a1, b[2], b[3]);
            }
        }
        __syncthreads();
    }

    // epilogue: BN + leaky, col-major fp16 act
    const int g = lane >> 2;
#pragma unroll
    for (int ni = 0; ni < 4; ni++) {
        const int n = n0 + wn * 32 + ni * 8 + (lane & 3) * 2;
        const float sc0 = g_d1sc[n], sc1 = g_d1sc[n + 1];
        const float sh0 = g_d1sh[n], sh1 = g_d1sh[n + 1];
#pragma unroll
        for (int mi = 0; mi < 2; mi++) {
#pragma unroll
            for (int half = 0; half < 2; half++) {
                const int row = m0 + wm * 32 + mi * 16 + g + half * 8;
                float v0 = acc[mi][ni][half * 2 + 0] * sc0 + sh0;
                float v1 = acc[mi][ni][half * 2 + 1] * sc1 + sh1;
                v0 = (v0 >= 0.f) ? v0 : 0.2f * v0;
                v1 = (v1 >= 0.f) ? v1 : 0.2f * v1;
                g_act[(size_t)n * BATCH + row] = __float2half_rn(v0);
                g_act[(size_t)(n + 1) * BATCH + row] = __float2half_rn(v1);
            }
        }
    }
}

// ---------------- Dense2 + softmax (col-major fp16 h2) ----------------
__global__ __launch_bounds__(256) void dense2_softmax_kernel(
    const float* __restrict__ Wd2, const float* __restrict__ bd2, float* __restrict__ out) {
    __shared__ float Ws[H2 * NCLS];
    __shared__ float bs[NCLS];
    int tid = threadIdx.x;
    for (int i = tid; i < H2 * NCLS; i += blockDim.x) Ws[i] = Wd2[i];
    if (tid < NCLS) bs[tid] = bd2[tid];
    __syncthreads();
    int row = blockIdx.x * blockDim.x + tid;
    const __half* hh = g_h2[0];  // t=15 writes buffer 0
    float acc[NCLS];
#pragma unroll
    for (int j = 0; j < NCLS; j++) acc[j] = bs[j];
#pragma unroll
    for (int k = 0; k < H2; k++) {
        float xv = __half2float(hh[(size_t)k * BATCH + row]);
#pragma unroll
        for (int j = 0; j < NCLS; j++) acc[j] += xv * Ws[k * NCLS + j];
    }
    float m = acc[0];
#pragma unroll
    for (int j = 1; j < NCLS; j++) m = fmaxf(m, acc[j]);
    float ssum = 0.f;
#pragma unroll
    for (int j = 0; j < NCLS; j++) { acc[j] = expf(acc[j] - m); ssum += acc[j]; }
    float inv = 1.f / ssum;
#pragma unroll
    for (int j = 0; j < NCLS; j++) out[(size_t)row * NCLS + j] = acc[j] * inv;
}

// ---------------- launch ----------------
extern "C" void kernel_launch(void* const* d_in, const int* in_sizes, int n_in,
                              void* d_out, int out_size) {
    const float* x        = (const float*)d_in[0];
    const float* W_d1     = (const float*)d_in[1];
    const float* b_d1     = (const float*)d_in[2];
    const float* bn_gamma = (const float*)d_in[3];
    const float* bn_beta  = (const float*)d_in[4];
    const float* bn_mean  = (const float*)d_in[5];
    const float* bn_var   = (const float*)d_in[6];
    const float* Wx1      = (const float*)d_in[7];
    const float* Wh1      = (const float*)d_in[8];
    const float* b1       = (const float*)d_in[9];
    const float* Wx2      = (const float*)d_in[10];
    const float* Wh2      = (const float*)d_in[11];
    const float* b2       = (const float*)d_in[12];
    const float* W_d2     = (const float*)d_in[13];
    const float* b_d2     = (const float*)d_in[14];
    float* out = (float*)d_out;

    cudaFuncSetAttribute(dense1_kernel, cudaFuncAttributeMaxDynamicSharedMemorySize, SMD);
    cudaFuncSetAttribute(lstm1_first_kernel, cudaFuncAttributeMaxDynamicSharedMemorySize, SM_STEP);
    cudaFuncSetAttribute(step_kernel, cudaFuncAttributeMaxDynamicSharedMemorySize, SM_STEP);

    prepack_kernel<<<256, 256>>>(Wx1, Wh1, b1, Wx2, Wh2, b2, W_d1, b_d1,
                                 bn_gamma, bn_beta, bn_mean, bn_var);
    init_state_kernel<<<2048, 256>>>();
    dense1_kernel<<<dim3(BATCH / 128, D_DENSE / 128), 512, SMD>>>(x);
    lstm1_first_kernel<<<1024, 512, SM_STEP>>>();
    for (int t = 0; t < TSTEPS; t++) {
        step_kernel<<<1280, 512, SM_STEP>>>(t, (t < TSTEPS - 1) ? 1 : 0);
    }
    dense2_softmax_kernel<<<BATCH / 256, 256>>>(W_d2, b_d2, out);
}

// round 16
// speedup vs baseline: 2.0702x; 1.1123x over previous
#include <cuda_runtime.h>
#include <cuda_bf16.h>
#include <cuda_fp16.h>
#include <math.h>
#include <stdint.h>

#define BATCH   32768
#define D_IN    512
#define D_DENSE 256
#define TSTEPS  16
#define FEAT    16
#define H1      128
#define H2      32
#define NCLS    10

// ---------------- state: COLUMN-major [feature][BATCH], single fp16 ----------------
__device__ __half g_act[D_DENSE * BATCH];
__device__ __half g_h1[2][H1 * BATCH];
__device__ __half g_h2[2][H2 * BATCH];
__device__ float g_c1[H1 * BATCH], g_c2[H2 * BATCH];

// prepacked weights: single fp16
__device__ __half g_Wp1[(4 * H1) * (FEAT + H1)];   // [512][144] gate-interleaved
__device__ __half g_Wp2[(4 * H2) * (H1 + H2)];     // [128][160]
__device__ __half g_WpD[D_DENSE * D_IN];           // [256][512] row n, K cols
__device__ float g_bc1[4 * H1], g_bc2[4 * H2];
__device__ float g_d1sc[D_DENSE], g_d1sh[D_DENSE];

// ---------------- helpers ----------------
__device__ __forceinline__ uint32_t smem_u32(const void* p) {
    uint32_t a;
    asm("{ .reg .u64 t; cvta.to.shared.u64 t, %1; cvt.u32.u64 %0, t; }" : "=r"(a) : "l"(p));
    return a;
}
__device__ __forceinline__ float ftanh(float x) {
    float y;
    asm("tanh.approx.f32 %0, %1;" : "=f"(y) : "f"(x));
    return y;
}
__device__ __forceinline__ float fsigm(float x) { return 0.5f * ftanh(0.5f * x) + 0.5f; }

__device__ __forceinline__ void ldsm4(uint32_t* r, uint32_t addr) {
    asm volatile("ldmatrix.sync.aligned.m8n8.x4.shared.b16 {%0,%1,%2,%3}, [%4];"
                 : "=r"(r[0]), "=r"(r[1]), "=r"(r[2]), "=r"(r[3]) : "r"(addr));
}
__device__ __forceinline__ void ldsm4t(uint32_t* r, uint32_t addr) {
    asm volatile("ldmatrix.sync.aligned.m8n8.x4.trans.shared.b16 {%0,%1,%2,%3}, [%4];"
                 : "=r"(r[0]), "=r"(r[1]), "=r"(r[2]), "=r"(r[3]) : "r"(addr));
}
__device__ __forceinline__ void mma16816h(float* d, const uint32_t* a, uint32_t b0, uint32_t b1) {
    asm volatile(
        "mma.sync.aligned.m16n8k16.row.col.f32.f16.f16.f32 "
        "{%0,%1,%2,%3}, {%4,%5,%6,%7}, {%8,%9}, {%0,%1,%2,%3};"
        : "+f"(d[0]), "+f"(d[1]), "+f"(d[2]), "+f"(d[3])
        : "r"(a[0]), "r"(a[1]), "r"(a[2]), "r"(a[3]), "r"(b0), "r"(b1));
}
__device__ __forceinline__ void cp16(uint32_t dst, const void* src) {
    asm volatile("cp.async.cg.shared.global [%0], [%1], 16;" :: "r"(dst), "l"(src));
}
#define CP_COMMIT() asm volatile("cp.async.commit_group;" ::: "memory")
#define CP_WAIT(n)  asm volatile("cp.async.wait_group %0;" :: "n"(n) : "memory")

// ===== fused LSTM step: single fp16, 2-chunk K-split + c-tile smem prefetch =====
// 512 threads, 16 warps 4Mx4N, warp tile 32x32, CTA tile 128x128.
#define SROW 136
#define SBC  88
#define ASTG (80 * SROW * 2)
#define BSTG (128 * SBC * 2)
#define STG  (ASTG + BSTG)           // 44288
#define CROW 132                     // c smem row: 128 floats + 4 pad
#define CS_OFF (2 * STG)             // 88576
#define CSZ (32 * CROW * 4)          // 16896
#define SM_STEP (CS_OFF + CSZ)       // 105472

template <int KX, int HID, int BK0>
__device__ __forceinline__ void lstm_body(int t, int m0, int n0, char* smemc) {
    constexpr int K = KX + HID;
    constexpr int BK1 = K - BK0;
    const int tid = threadIdx.x;
    const int lane = tid & 31, wid = tid >> 5;
    const int wm = wid & 3, wn = wid >> 2;    // 4 x 4
    const uint32_t sbase = smem_u32(smemc);
    const int p = t & 1;

    const __half *xsrc, *hsrc;
    __half* hdst;
    float* cbuf;
    const __half* W;
    const float* bias;
    int xoff;
    if (HID == H1) {
        xsrc = g_act; xoff = t * FEAT;
        hsrc = g_h1[p]; hdst = g_h1[p ^ 1];
        cbuf = g_c1; W = g_Wp1; bias = g_bc1;
    } else {
        xsrc = g_h1[p ^ 1]; xoff = 0;
        hsrc = g_h2[p]; hdst = g_h2[p ^ 1];
        cbuf = g_c2; W = g_Wp2; bias = g_bc2;
    }
    const int u0 = n0 >> 2;   // first unit of this CTA's gate block

    // ---- chunk 0 load ----
    {
        const uint32_t As = sbase, Bs = sbase + ASTG;
#pragma unroll
        for (int task = tid; task < BK0 * 16; task += 512) {
            const int k = task >> 4, mg = task & 15;
            const __half* src = (k < KX)
                ? xsrc + (size_t)(xoff + k) * BATCH + m0 + mg * 8
                : hsrc + (size_t)(k - KX) * BATCH + m0 + mg * 8;
            cp16(As + (uint32_t)(k * SROW + mg * 8) * 2, src);
        }
#pragma unroll
        for (int task = tid; task < 128 * (BK0 / 8); task += 512) {
            const int n = task / (BK0 / 8), gg = task % (BK0 / 8);
            cp16(Bs + (uint32_t)(n * SBC + gg * 8) * 2,
                 W + (size_t)(n0 + n) * K + gg * 8);
        }
    }
    CP_COMMIT();
    // ---- chunk 1 load + c-tile prefetch ----
    {
        const uint32_t As = sbase + STG, Bs = sbase + STG + ASTG;
#pragma unroll
        for (int task = tid; task < BK1 * 16; task += 512) {
            const int k = task >> 4, mg = task & 15;
            const int col = BK0 + k;
            const __half* src = (col < KX)
                ? xsrc + (size_t)(xoff + col) * BATCH + m0 + mg * 8
                : hsrc + (size_t)(col - KX) * BATCH + m0 + mg * 8;
            cp16(As + (uint32_t)(k * SROW + mg * 8) * 2, src);
        }
#pragma unroll
        for (int task = tid; task < 128 * (BK1 / 8); task += 512) {
            const int n = task / (BK1 / 8), gg = task % (BK1 / 8);
            cp16(Bs + (uint32_t)(n * SBC + gg * 8) * 2,
                 W + (size_t)(n0 + n) * K + BK0 + gg * 8);
        }
        // c-tile: 32 units x 128 rows fp32 (16B = 4 floats per task)
#pragma unroll
        for (int task = tid; task < 32 * 32; task += 512) {
            const int ul = task >> 5, gg = task & 31;
            cp16(sbase + CS_OFF + (uint32_t)(ul * CROW + gg * 4) * 4,
                 cbuf + (size_t)(u0 + ul) * BATCH + m0 + gg * 4);
        }
    }
    CP_COMMIT();

    const uint32_t arow = (uint32_t)((lane & 7) + ((lane >> 4) << 3));
    const uint32_t acol = (uint32_t)(wm * 32 + (((lane >> 3) & 1) << 3));
    const uint32_t brow = (uint32_t)(wn * 32 + ((lane >> 4) << 3) + (lane & 7));
    const uint32_t bcol8 = (uint32_t)(((lane >> 3) & 1) << 3);
    float acc[2][4][4] = {};

    CP_WAIT(1);
    __syncthreads();
#pragma unroll
    for (int kk = 0; kk < BK0 / 16; kk++) {
        uint32_t a0[4], a1[4];
        const uint32_t hr = (uint32_t)(kk * 16) + arow;
        ldsm4t(a0, sbase + (hr * SROW + acol) * 2);
        ldsm4t(a1, sbase + (hr * SROW + acol + 16) * 2);
        const uint32_t cofs = (uint32_t)(kk * 16) + bcol8;
#pragma unroll
        for (int nj = 0; nj < 2; nj++) {
            uint32_t b[4];
            ldsm4(b, sbase + ASTG + ((brow + nj * 16) * SBC + cofs) * 2);
            mma16816h(acc[0][2 * nj], a0, b[0], b[1]);
            mma16816h(acc[0][2 * nj + 1], a0, b[2], b[3]);
            mma16816h(acc[1][2 * nj], a1, b[0], b[1]);
            mma16816h(acc[1][2 * nj + 1], a1, b[2], b[3]);
        }
    }
    CP_WAIT(0);
    __syncthreads();
#pragma unroll
    for (int kk = 0; kk < BK1 / 16; kk++) {
        uint32_t a0[4], a1[4];
        const uint32_t hr = (uint32_t)(kk * 16) + arow;
        ldsm4t(a0, sbase + STG + (hr * SROW + acol) * 2);
        ldsm4t(a1, sbase + STG + (hr * SROW + acol + 16) * 2);
        const uint32_t cofs = (uint32_t)(kk * 16) + bcol8;
#pragma unroll
        for (int nj = 0; nj < 2; nj++) {
            uint32_t b[4];
            ldsm4(b, sbase + STG + ASTG + ((brow + nj * 16) * SBC + cofs) * 2);
            mma16816h(acc[0][2 * nj], a0, b[0], b[1]);
            mma16816h(acc[0][2 * nj + 1], a0, b[2], b[3]);
            mma16816h(acc[1][2 * nj], a1, b[0], b[1]);
            mma16816h(acc[1][2 * nj + 1], a1, b[2], b[3]);
        }
    }

    // epilogue: c read from smem (prefetched); stores direct to gmem
    const float* const cs = (const float*)(smemc + CS_OFF);
    const int g = lane >> 2;
    const bool odd = lane & 1;
#pragma unroll
    for (int ni = 0; ni < 4; ni++) {
        const int ul = wn * 8 + ni * 2 + ((lane & 2) >> 1);
        const int u = u0 + ul;
        const float4 bb = *(const float4*)(bias + 4 * u);
#pragma unroll
        for (int mi = 0; mi < 2; mi++) {
            const float d0 = acc[mi][ni][0], d1 = acc[mi][ni][1];
            const float d2 = acc[mi][ni][2], d3 = acc[mi][ni][3];
            const float s0 = __shfl_xor_sync(0xffffffffu, odd ? d0 : d2, 1);
            const float s1 = __shfl_xor_sync(0xffffffffu, odd ? d1 : d3, 1);
            const float zi = (odd ? s0 : d0) + bb.x;
            const float zf = (odd ? s1 : d1) + bb.y;
            const float zg = (odd ? d2 : s0) + bb.z;
            const float zo = (odd ? d3 : s1) + bb.w;
            const int rl = wm * 32 + mi * 16 + g + (odd ? 8 : 0);
            const float ig = fsigm(zi);
            const float fg = fsigm(zf);
            const float gg = ftanh(zg);
            const float og = fsigm(zo);
            const float cn = fg * cs[ul * CROW + rl] + ig * gg;
            const size_t off = (size_t)u * BATCH + m0 + rl;
            cbuf[off] = cn;
            hdst[off] = __float2half_rn(og * ftanh(cn));
        }
    }
}

__global__ __launch_bounds__(512, 2) void lstm1_first_kernel() {
    extern __shared__ char smem[];
    lstm_body<FEAT, H1, 80>(0, (blockIdx.x & 255) * 128, (blockIdx.x >> 8) * 128, smem);
}

__global__ __launch_bounds__(512, 2) void step_kernel(int t, int do_l1) {
    extern __shared__ char smem[];
    if (blockIdx.x < 256) {
        lstm_body<H1, H2, 80>(t, blockIdx.x * 128, 0, smem);
    } else if (do_l1) {
        const int bx = blockIdx.x - 256;
        lstm_body<FEAT, H1, 80>(t + 1, (bx & 255) * 128, (bx >> 8) * 128, smem);
    }
}

// ---------------- init & prepack ----------------
__global__ void init_state_kernel() {
    int idx = blockIdx.x * blockDim.x + threadIdx.x;
    int stride = gridDim.x * blockDim.x;
    const __half z = __float2half(0.f);
    for (int i = idx; i < BATCH * H1; i += stride) { g_h1[0][i] = z; g_c1[i] = 0.f; }
    for (int i = idx; i < BATCH * H2; i += stride) { g_h2[0][i] = z; g_c2[i] = 0.f; }
}

__global__ void prepack_kernel(const float* __restrict__ Wx1, const float* __restrict__ Wh1,
                               const float* __restrict__ b1,
                               const float* __restrict__ Wx2, const float* __restrict__ Wh2,
                               const float* __restrict__ b2,
                               const float* __restrict__ W_d1, const float* __restrict__ b_d1,
                               const float* __restrict__ gamma, const float* __restrict__ beta,
                               const float* __restrict__ mean, const float* __restrict__ var) {
    int idx = blockIdx.x * blockDim.x + threadIdx.x;
    int stride = gridDim.x * blockDim.x;
    {
        constexpr int K = FEAT + H1;
        for (int i = idx; i < 4 * H1 * K; i += stride) {
            int n = i / K, k = i % K;
            int u = n >> 2, g = n & 3, src = g * H1 + u;
            float w = (k < FEAT) ? Wx1[k * 4 * H1 + src] : Wh1[(k - FEAT) * 4 * H1 + src];
            g_Wp1[(size_t)n * K + k] = __float2half_rn(w);
        }
        for (int i = idx; i < 4 * H1; i += stride) {
            int u = i >> 2, g = i & 3;
            g_bc1[i] = b1[g * H1 + u];
        }
    }
    {
        constexpr int K = H1 + H2;
        for (int i = idx; i < 4 * H2 * K; i += stride) {
            int n = i / K, k = i % K;
            int u = n >> 2, g = n & 3, src = g * H2 + u;
            float w = (k < H1) ? Wx2[k * 4 * H2 + src] : Wh2[(k - H1) * 4 * H2 + src];
            g_Wp2[(size_t)n * K + k] = __float2half_rn(w);
        }
        for (int i = idx; i < 4 * H2; i += stride) {
            int u = i >> 2, g = i & 3;
            g_bc2[i] = b2[g * H2 + u];
        }
    }
    for (int i = idx; i < D_DENSE * D_IN; i += stride) {
        int n = i / D_IN, k = i % D_IN;
        g_WpD[(size_t)n * D_IN + k] = __float2half_rn(W_d1[(size_t)k * D_DENSE + n]);
    }
    for (int i = idx; i < D_DENSE; i += stride) {
        float sc = gamma[i] * rsqrtf(var[i] + 1e-3f);
        g_d1sc[i] = sc;
        g_d1sh[i] = beta[i] + (b_d1[i] - mean[i]) * sc;
    }
}

// ---------------- Dense1 (R15 verified): single fp16, 512 thr 4Mx4N ----------------
#define D1S 136
#define D1_ASZ (128 * D1S * 2)
#define SMD (2 * D1_ASZ)   // 69632

__global__ __launch_bounds__(512, 2) void dense1_kernel(const float* __restrict__ x) {
    constexpr int KP = 128;
    extern __shared__ char smem[];
    const uint32_t Asm = smem_u32(smem);
    const uint32_t Bsm = Asm + D1_ASZ;
    const int tid = threadIdx.x;
    const int lane = tid & 31, wid = tid >> 5;
    const int wm = wid & 3, wn = wid >> 2;
    const int m0 = blockIdx.x * 128, n0 = blockIdx.y * 128;

    const uint32_t abase = Asm + ((((uint32_t)(wm * 32 + (lane & 15))) * D1S + ((lane >> 4) << 3)) << 1);
    const uint32_t brow = (uint32_t)(wn * 32 + ((lane >> 4) << 3) + (lane & 7));
    const uint32_t bcol8 = (uint32_t)(((lane >> 3) & 1) << 3);

    float acc[2][4][4] = {};
    for (int p = 0; p < 4; p++) {
        for (int task = tid; task < 128 * 16; task += 512) {
            const int r = task >> 4, o = task & 15;
            const float* src = x + (size_t)(m0 + r) * D_IN + p * KP + o * 8;
            const float4 v0 = *(const float4*)src;
            const float4 v1 = *(const float4*)(src + 4);
            __half h[8];
            h[0] = __float2half_rn(v0.x); h[1] = __float2half_rn(v0.y);
            h[2] = __float2half_rn(v0.z); h[3] = __float2half_rn(v0.w);
            h[4] = __float2half_rn(v1.x); h[5] = __float2half_rn(v1.y);
            h[6] = __float2half_rn(v1.z); h[7] = __float2half_rn(v1.w);
            *(uint4*)(smem + ((size_t)r * D1S + o * 8) * 2) = *(uint4*)h;
        }
        for (int task = tid; task < 128 * 16; task += 512) {
            const int n = task >> 4, gg = task & 15;
            cp16(Bsm + (uint32_t)(n * D1S + gg * 8) * 2,
                 g_WpD + (size_t)(n0 + n) * D_IN + p * KP + gg * 8);
        }
        CP_COMMIT();
        CP_WAIT(0);
        __syncthreads();
#pragma unroll
        for (int kk = 0; kk < KP / 16; kk++) {
            uint32_t a0[4], a1[4];
            ldsm4(a0, abase + (kk * 16) * 2);
            ldsm4(a1, abase + (16 * D1S + kk * 16) * 2);
            const uint32_t cofs = (uint32_t)(kk * 16) + bcol8;
#pragma unroll
            for (int nj = 0; nj < 2; nj++) {
                uint32_t b[4];
                ldsm4(b, Bsm + ((brow + nj * 16) * D1S + cofs) * 2);
                mma16816h(acc[0][2 * nj], a0, b[0], b[1]);
                mma16816h(acc[0][2 * nj + 1], a0, b[2], b[3]);
                mma16816h(acc[1][2 * nj], a1, b[0], b[1]);
                mma16816h(acc[1][2 * nj + 1], a1, b[2], b[3]);
            }
        }
        __syncthreads();
    }

    const int g = lane >> 2;
#pragma unroll
    for (int ni = 0; ni < 4; ni++) {
        const int n = n0 + wn * 32 + ni * 8 + (lane & 3) * 2;
        const float sc0 = g_d1sc[n], sc1 = g_d1sc[n + 1];
        const float sh0 = g_d1sh[n], sh1 = g_d1sh[n + 1];
#pragma unroll
        for (int mi = 0; mi < 2; mi++) {
#pragma unroll
            for (int half = 0; half < 2; half++) {
                const int row = m0 + wm * 32 + mi * 16 + g + half * 8;
                float v0 = acc[mi][ni][half * 2 + 0] * sc0 + sh0;
                float v1 = acc[mi][ni][half * 2 + 1] * sc1 + sh1;
                v0 = (v0 >= 0.f) ? v0 : 0.2f * v0;
                v1 = (v1 >= 0.f) ? v1 : 0.2f * v1;
                g_act[(size_t)n * BATCH + row] = __float2half_rn(v0);
                g_act[(size_t)(n + 1) * BATCH + row] = __float2half_rn(v1);
            }
        }
    }
}

// ---------------- Dense2 + softmax (col-major fp16 h2) ----------------
__global__ __launch_bounds__(256) void dense2_softmax_kernel(
    const float* __restrict__ Wd2, const float* __restrict__ bd2, float* __restrict__ out) {
    __shared__ float Ws[H2 * NCLS];
    __shared__ float bs[NCLS];
    int tid = threadIdx.x;
    for (int i = tid; i < H2 * NCLS; i += blockDim.x) Ws[i] = Wd2[i];
    if (tid < NCLS) bs[tid] = bd2[tid];
    __syncthreads();
    int row = blockIdx.x * blockDim.x + tid;
    const __half* hh = g_h2[0];  // t=15 writes buffer 0
    float acc[NCLS];
#pragma unroll
    for (int j = 0; j < NCLS; j++) acc[j] = bs[j];
#pragma unroll
    for (int k = 0; k < H2; k++) {
        float xv = __half2float(hh[(size_t)k * BATCH + row]);
#pragma unroll
        for (int j = 0; j < NCLS; j++) acc[j] += xv * Ws[k * NCLS + j];
    }
    float m = acc[0];
#pragma unroll
    for (int j = 1; j < NCLS; j++) m = fmaxf(m, acc[j]);
    float ssum = 0.f;
#pragma unroll
    for (int j = 0; j < NCLS; j++) { acc[j] = expf(acc[j] - m); ssum += acc[j]; }
    float inv = 1.f / ssum;
#pragma unroll
    for (int j = 0; j < NCLS; j++) out[(size_t)row * NCLS + j] = acc[j] * inv;
}

// ---------------- launch ----------------
extern "C" void kernel_launch(void* const* d_in, const int* in_sizes, int n_in,
                              void* d_out, int out_size) {
    const float* x        = (const float*)d_in[0];
    const float* W_d1     = (const float*)d_in[1];
    const float* b_d1     = (const float*)d_in[2];
    const float* bn_gamma = (const float*)d_in[3];
    const float* bn_beta  = (const float*)d_in[4];
    const float* bn_mean  = (const float*)d_in[5];
    const float* bn_var   = (const float*)d_in[6];
    const float* Wx1      = (const float*)d_in[7];
    const float* Wh1      = (const float*)d_in[8];
    const float* b1       = (const float*)d_in[9];
    const float* Wx2      = (const float*)d_in[10];
    const float* Wh2      = (const float*)d_in[11];
    const float* b2       = (const float*)d_in[12];
    const float* W_d2     = (const float*)d_in[13];
    const float* b_d2     = (const float*)d_in[14];
    float* out = (float*)d_out;

    cudaFuncSetAttribute(dense1_kernel, cudaFuncAttributeMaxDynamicSharedMemorySize, SMD);
    cudaFuncSetAttribute(lstm1_first_kernel, cudaFuncAttributeMaxDynamicSharedMemorySize, SM_STEP);
    cudaFuncSetAttribute(step_kernel, cudaFuncAttributeMaxDynamicSharedMemorySize, SM_STEP);

    prepack_kernel<<<256, 256>>>(Wx1, Wh1, b1, Wx2, Wh2, b2, W_d1, b_d1,
                                 bn_gamma, bn_beta, bn_mean, bn_var);
    init_state_kernel<<<2048, 256>>>();
    dense1_kernel<<<dim3(BATCH / 128, D_DENSE / 128), 512, SMD>>>(x);
    lstm1_first_kernel<<<1024, 512, SM_STEP>>>();
    for (int t = 0; t < TSTEPS; t++) {
        step_kernel<<<1280, 512, SM_STEP>>>(t, (t < TSTEPS - 1) ? 1 : 0);
    }
    dense2_softmax_kernel<<<BATCH / 256, 256>>>(W_d2, b_d2, out);
}